// round 4
// baseline (speedup 1.0000x reference)
#include <cuda_runtime.h>

#define NN 50000
#define EE 800000
#define BBATCH 256
#define TSTEPS 50
#define FM 0xffffffffu

__device__ __align__(16) float d_xw[NN*128];
__device__ __align__(16) float d_h[NN*128];
__device__ __align__(16) float d_hw[NN*128];
__device__ __align__(16) float d_asrc[NN*4];
__device__ __align__(16) float d_adst[NN*4];
__device__ __align__(16) float d_ex[EE*4];
__device__ float d_dinv[NN];
__device__ int   d_deg[NN];
__device__ int   d_rowptr[NN+1];
__device__ int   d_cursor[NN];
__device__ int   d_colsrc[EE];
__device__ int   d_bsum[256], d_boff[256];
__device__ float d_gnum[BBATCH*128];
__device__ float d_gden[BBATCH];
__device__ __align__(16) float d_xp[BBATCH*TSTEPS*512];
__device__ float d_hT[BBATCH*128];

__device__ __forceinline__ float sigf(float x){ return __fdividef(1.f, 1.f + __expf(-x)); }
__device__ __forceinline__ float tanhfa(float x){ float e=__expf(2.f*x); return 1.f - __fdividef(2.f, e+1.f); }

__device__ __forceinline__ void ffma2(unsigned long long& d, unsigned long long a, unsigned long long b){
    asm("fma.rn.f32x2 %0, %1, %2, %0;" : "+l"(d) : "l"(a), "l"(b));
}
__device__ __forceinline__ float pairsum(unsigned long long v){
    float2 f; __builtin_memcpy(&f, &v, 8); return f.x + f.y;
}

__global__ void k_init(){
    int i = blockIdx.x*256 + threadIdx.x;
    if (i < NN) d_deg[i] = 0;
    if (i < BBATCH*128) d_gnum[i]=0.f;
    if (i < BBATCH) d_gden[i]=0.f;
}

__global__ void k_count(const int* __restrict__ ei){
    int i = blockIdx.x*256 + threadIdx.x;
    if (i < EE) atomicAdd(&d_deg[ei[EE+i]], 1);
}

__global__ void k_scan1(){
    __shared__ int s[256];
    int tid = threadIdx.x;
    int i = blockIdx.x*256 + tid;
    int v = (i < NN) ? d_deg[i] : 0;
    s[tid] = v; __syncthreads();
    for (int off=1; off<256; off<<=1){
        int t = (tid>=off) ? s[tid-off] : 0;
        __syncthreads(); s[tid] += t; __syncthreads();
    }
    if (i < NN) d_rowptr[i+1] = s[tid];
    if (tid == 255) d_bsum[blockIdx.x] = s[255];
}

__global__ void k_scan2(){
    __shared__ int s[256];
    int tid = threadIdx.x;
    int v = (tid < 196) ? d_bsum[tid] : 0;
    s[tid] = v; __syncthreads();
    for (int off=1; off<256; off<<=1){
        int t = (tid>=off) ? s[tid-off] : 0;
        __syncthreads(); s[tid] += t; __syncthreads();
    }
    if (tid < 196) d_boff[tid] = s[tid] - v;
}

__global__ void k_scan3(){
    int i = blockIdx.x*256 + threadIdx.x;
    if (i < NN) d_rowptr[i+1] += d_boff[blockIdx.x];
    if (i == 0) d_rowptr[0] = 0;
}

__global__ void k_prep(){
    int i = blockIdx.x*256 + threadIdx.x;
    if (i >= NN) return;
    int a = d_rowptr[i], b = d_rowptr[i+1];
    d_cursor[i] = a;
    d_dinv[i] = rsqrtf((float)(b - a + 1));
}

// GEMM v2: Y = X @ W using f32x2 packed FMA with transposed W in smem.
// Block: 256 threads = 8 warps; tile 32 rows x 128 cols; thread owns 4 rows x 4 cols.
// mode0: X=Xp, Y=d_xw + attention epilogue; mode1: X=d_h, Y=d_hw
__global__ void __launch_bounds__(256,2) k_gemm(const float* __restrict__ Xp,
                       const float* __restrict__ W,
                       const float* __restrict__ attS, const float* __restrict__ attD, int mode){
    extern __shared__ float sm[];
    float* Wt = sm;              // 128 x 132 transposed: Wt[c*132+k] = W[k*128+c]
    float* xs = sm + 128*132;    // 32 x 132
    const float* X = mode ? d_h : Xp;
    float* Y = mode ? d_hw : d_xw;
    int tid = threadIdx.x, cg = tid & 31, rg = tid >> 5;

    // staged transpose: coalesced load 32 rows into xs, scatter into Wt
    for (int blk = 0; blk < 4; blk++){
        __syncthreads();
        for (int i = tid; i < 4096; i += 256){
            int r = i >> 7, k = i & 127;
            xs[r*132 + k] = W[(blk*32 + r)*128 + k];
        }
        __syncthreads();
        for (int i = tid; i < 4096; i += 256){
            int r = i >> 7, c = i & 127;
            Wt[c*132 + blk*32 + r] = xs[r*132 + c];
        }
    }
    float as0=0,as1=0,as2=0,as3=0, ad0=0,ad1=0,ad2=0,ad3=0;
    if (!mode){
        as0=attS[cg*4]; as1=attS[cg*4+1]; as2=attS[cg*4+2]; as3=attS[cg*4+3];
        ad0=attD[cg*4]; ad1=attD[cg*4+1]; ad2=attD[cg*4+2]; ad3=attD[cg*4+3];
    }

    const unsigned long long* w0p = (const unsigned long long*)&Wt[(cg*4+0)*132];
    const unsigned long long* w1p = (const unsigned long long*)&Wt[(cg*4+1)*132];
    const unsigned long long* w2p = (const unsigned long long*)&Wt[(cg*4+2)*132];
    const unsigned long long* w3p = (const unsigned long long*)&Wt[(cg*4+3)*132];
    const unsigned long long* x0p = (const unsigned long long*)&xs[(rg*4+0)*132];
    const unsigned long long* x1p = (const unsigned long long*)&xs[(rg*4+1)*132];
    const unsigned long long* x2p = (const unsigned long long*)&xs[(rg*4+2)*132];
    const unsigned long long* x3p = (const unsigned long long*)&xs[(rg*4+3)*132];

    for (int chunk = blockIdx.x; chunk < (NN+31)/32; chunk += gridDim.x){
        int row0 = chunk*32;
        __syncthreads();
        for (int i = tid; i < 4096; i += 256){
            int r = i >> 7, k = i & 127;
            int gr = row0 + r;
            xs[r*132 + k] = (gr < NN) ? X[gr*128 + k] : 0.f;
        }
        __syncthreads();
        unsigned long long acc[4][4];
        #pragma unroll
        for (int r=0;r<4;r++)
            #pragma unroll
            for (int c=0;c<4;c++) acc[r][c] = 0ull;
        #pragma unroll 8
        for (int k2=0; k2<64; k2++){
            unsigned long long w0 = w0p[k2], w1 = w1p[k2], w2 = w2p[k2], w3 = w3p[k2];
            unsigned long long xa = x0p[k2], xb = x1p[k2], xc = x2p[k2], xd = x3p[k2];
            ffma2(acc[0][0], xa, w0); ffma2(acc[0][1], xa, w1); ffma2(acc[0][2], xa, w2); ffma2(acc[0][3], xa, w3);
            ffma2(acc[1][0], xb, w0); ffma2(acc[1][1], xb, w1); ffma2(acc[1][2], xb, w2); ffma2(acc[1][3], xb, w3);
            ffma2(acc[2][0], xc, w0); ffma2(acc[2][1], xc, w1); ffma2(acc[2][2], xc, w2); ffma2(acc[2][3], xc, w3);
            ffma2(acc[3][0], xd, w0); ffma2(acc[3][1], xd, w1); ffma2(acc[3][2], xd, w2); ffma2(acc[3][3], xd, w3);
        }
        #pragma unroll
        for (int r=0;r<4;r++){
            int grow = row0 + rg*4 + r;
            float o0 = pairsum(acc[r][0]), o1 = pairsum(acc[r][1]);
            float o2 = pairsum(acc[r][2]), o3 = pairsum(acc[r][3]);
            if (grow < NN)
                *(float4*)&Y[grow*128 + cg*4] = make_float4(o0,o1,o2,o3);
            if (!mode){
                float s = o0*as0 + o1*as1 + o2*as2 + o3*as3;
                float d = o0*ad0 + o1*ad1 + o2*ad2 + o3*ad3;
                #pragma unroll
                for (int off=4; off; off>>=1){
                    s += __shfl_xor_sync(FM, s, off);
                    d += __shfl_xor_sync(FM, d, off);
                }
                if ((cg & 7) == 0 && grow < NN){
                    d_asrc[grow*4 + (cg>>3)] = s;
                    d_adst[grow*4 + (cg>>3)] = d;
                }
            }
        }
    }
}

__global__ void k_scatter(const int* __restrict__ ei){
    int i = blockIdx.x*256 + threadIdx.x;
    if (i >= EE) return;
    int s = ei[i], d = ei[EE+i];
    int pos = atomicAdd(&d_cursor[d], 1);
    d_colsrc[pos] = s;
    float4 as = *(const float4*)&d_asrc[s*4];
    float4 ad = *(const float4*)&d_adst[d*4];
    float e0 = as.x+ad.x; e0 = e0>0.f? e0 : 0.2f*e0;
    float e1 = as.y+ad.y; e1 = e1>0.f? e1 : 0.2f*e1;
    float e2 = as.z+ad.z; e2 = e2>0.f? e2 : 0.2f*e2;
    float e3 = as.w+ad.w; e3 = e3>0.f? e3 : 0.2f*e3;
    float4 ex = make_float4(__expf(e0),__expf(e1),__expf(e2),__expf(e3));
    *(float4*)&d_ex[pos*4] = ex;
}

__global__ void k_gat(const float* __restrict__ gatb,
                      const float* __restrict__ g1, const float* __restrict__ b1,
                      const float* __restrict__ m1, const float* __restrict__ v1){
    __shared__ float sc[128], sh[128], gb[128];
    int tid = threadIdx.x;
    if (tid < 128){
        float s = g1[tid]*rsqrtf(v1[tid]+1e-5f);
        sc[tid]=s; sh[tid]=b1[tid]-m1[tid]*s; gb[tid]=gatb[tid];
    }
    __syncthreads();
    int lane = tid & 31;
    int node = blockIdx.x*8 + (tid>>5);
    if (node >= NN) return;
    int begin = d_rowptr[node], end = d_rowptr[node+1];
    float n0=0,n1=0,n2=0,n3=0;
    float dn0=0,dn1=0,dn2=0,dn3=0;
    for (int base = begin; base < end; base += 32){
        int idx = base + lane;
        int sl = 0; float4 exl = make_float4(0,0,0,0);
        if (idx < end){
            sl = d_colsrc[idx];
            exl = *(const float4*)&d_ex[idx*4];
            dn0+=exl.x; dn1+=exl.y; dn2+=exl.z; dn3+=exl.w;
        }
        int cnt = min(32, end-base);
        for (int j=0;j<cnt;j++){
            int sj = __shfl_sync(FM, sl, j);
            float a0=__shfl_sync(FM,exl.x,j), a1=__shfl_sync(FM,exl.y,j);
            float a2=__shfl_sync(FM,exl.z,j), a3=__shfl_sync(FM,exl.w,j);
            float aj = lane<8? a0 : lane<16? a1 : lane<24? a2 : a3;
            float4 xv = *(const float4*)&d_xw[sj*128 + lane*4];
            n0 += xv.x*aj; n1 += xv.y*aj; n2 += xv.z*aj; n3 += xv.w*aj;
        }
    }
    #pragma unroll
    for (int off=16; off; off>>=1){
        dn0 += __shfl_xor_sync(FM,dn0,off); dn1 += __shfl_xor_sync(FM,dn1,off);
        dn2 += __shfl_xor_sync(FM,dn2,off); dn3 += __shfl_xor_sync(FM,dn3,off);
    }
    float4 as = *(const float4*)&d_asrc[node*4];
    float4 ad = *(const float4*)&d_adst[node*4];
    float e0=as.x+ad.x; e0=e0>0.f?e0:0.2f*e0; float x0=__expf(e0);
    float e1=as.y+ad.y; e1=e1>0.f?e1:0.2f*e1; float x1=__expf(e1);
    float e2=as.z+ad.z; e2=e2>0.f?e2:0.2f*e2; float x2=__expf(e2);
    float e3=as.w+ad.w; e3=e3>0.f?e3:0.2f*e3; float x3=__expf(e3);
    dn0+=x0; dn1+=x1; dn2+=x2; dn3+=x3;
    float4 xv = *(const float4*)&d_xw[node*128 + lane*4];
    float aself = lane<8? x0 : lane<16? x1 : lane<24? x2 : x3;
    n0 += xv.x*aself; n1 += xv.y*aself; n2 += xv.z*aself; n3 += xv.w*aself;
    float hd = lane<8? dn0 : lane<16? dn1 : lane<24? dn2 : dn3;
    float inv = 1.0f/(hd + 1e-16f);
    int col = lane*4;
    float o0 = n0*inv + gb[col];   o0 = o0>0.f? o0 : expm1f(o0); o0 = o0*sc[col]+sh[col];
    float o1 = n1*inv + gb[col+1]; o1 = o1>0.f? o1 : expm1f(o1); o1 = o1*sc[col+1]+sh[col+1];
    float o2 = n2*inv + gb[col+2]; o2 = o2>0.f? o2 : expm1f(o2); o2 = o2*sc[col+2]+sh[col+2];
    float o3 = n3*inv + gb[col+3]; o3 = o3>0.f? o3 : expm1f(o3); o3 = o3*sc[col+3]+sh[col+3];
    *(float4*)&d_h[node*128 + col] = make_float4(o0,o1,o2,o3);
}

__global__ void k_gcn(const int* __restrict__ batch,
                      const float* __restrict__ gcnb,
                      const float* __restrict__ g2, const float* __restrict__ b2,
                      const float* __restrict__ m2, const float* __restrict__ v2,
                      const float* __restrict__ gateW, const float* __restrict__ gateb){
    __shared__ float sc[128], sh[128], gb[128], gw[128];
    int tid = threadIdx.x;
    if (tid < 128){
        float s = g2[tid]*rsqrtf(v2[tid]+1e-5f);
        sc[tid]=s; sh[tid]=b2[tid]-m2[tid]*s; gb[tid]=gcnb[tid]; gw[tid]=gateW[tid];
    }
    __syncthreads();
    int lane = tid & 31;
    int node = blockIdx.x*8 + (tid>>5);
    if (node >= NN) return;
    int begin = d_rowptr[node], end = d_rowptr[node+1];
    float did = d_dinv[node];
    float a0=0,a1=0,a2=0,a3=0;
    for (int base = begin; base < end; base += 32){
        int idx = base + lane;
        int sl = 0; float dsl = 0.f;
        if (idx < end){ sl = d_colsrc[idx]; dsl = d_dinv[sl]; }
        int cnt = min(32, end-base);
        for (int j=0;j<cnt;j++){
            int sj = __shfl_sync(FM, sl, j);
            float ds = __shfl_sync(FM, dsl, j);
            float4 hv = *(const float4*)&d_hw[sj*128 + lane*4];
            a0 += hv.x*ds; a1 += hv.y*ds; a2 += hv.z*ds; a3 += hv.w*ds;
        }
    }
    int col = lane*4;
    float4 sv = *(const float4*)&d_hw[node*128 + col];
    float h0 = did*(a0 + did*sv.x) + gb[col];
    float h1 = did*(a1 + did*sv.y) + gb[col+1];
    float h2v = did*(a2 + did*sv.z) + gb[col+2];
    float h3 = did*(a3 + did*sv.w) + gb[col+3];
    h0 = h0>0.f? h0 : expm1f(h0); h0 = h0*sc[col]+sh[col];
    h1 = h1>0.f? h1 : expm1f(h1); h1 = h1*sc[col+1]+sh[col+1];
    h2v = h2v>0.f? h2v : expm1f(h2v); h2v = h2v*sc[col+2]+sh[col+2];
    h3 = h3>0.f? h3 : expm1f(h3); h3 = h3*sc[col+3]+sh[col+3];
    float g = h0*gw[col] + h1*gw[col+1] + h2v*gw[col+2] + h3*gw[col+3];
    #pragma unroll
    for (int off=16; off; off>>=1) g += __shfl_xor_sync(FM, g, off);
    g += gateb[0];
    float p = __expf(g);
    int b = batch[node];
    if (lane == 0) atomicAdd(&d_gden[b], p);
    atomicAdd(&d_gnum[b*128+col],   p*h0);
    atomicAdd(&d_gnum[b*128+col+1], p*h1);
    atomicAdd(&d_gnum[b*128+col+2], p*h2v);
    atomicAdd(&d_gnum[b*128+col+3], p*h3);
}

__global__ void k_xp(const float* __restrict__ quant, const float* __restrict__ Wih,
                     const float* __restrict__ bih, const float* __restrict__ bhh){
    __shared__ float qS[TSTEPS*32];
    int b = blockIdx.x, g = threadIdx.x;
    for (int i = g; i < TSTEPS*32; i += 512) qS[i] = quant[b*TSTEPS*32 + i];
    float4 wr[8];
    #pragma unroll
    for (int q=0;q<8;q++) wr[q] = *(const float4*)&Wih[g*32 + q*4];
    float bias = bih[g] + bhh[g];
    __syncthreads();
    const float4* qS4 = (const float4*)qS;
    for (int t=0; t<TSTEPS; t++){
        float acc = bias;
        #pragma unroll
        for (int q=0;q<8;q++){
            float4 xv = qS4[t*8+q];
            acc += wr[q].x*xv.x + wr[q].y*xv.y + wr[q].z*xv.z + wr[q].w*xv.w;
        }
        d_xp[(b*TSTEPS + t)*512 + g] = acc;
    }
}

__global__ void __cluster_dims__(2,1,1) k_lstmp(const float* __restrict__ Whh){
    extern __shared__ float sm[];
    float* ws   = sm;            // 256 rows x 132 (padded)
    float* hS   = sm + 33792;    // 4 x 132
    float* gbuf = sm + 34320;    // 256 x 4
    int tid = threadIdx.x;
    unsigned int rank;
    asm("mov.u32 %0, %%cluster_ctarank;" : "=r"(rank));
    int U0 = (int)rank * 64;
    int b0 = (blockIdx.x >> 1) * 4;
    int g  = tid >> 6, ju = tid & 63;

    {
        const float4* src = (const float4*)&Whh[(g*128 + U0 + ju)*128];
        float4* dst = (float4*)&ws[tid*132];
        #pragma unroll
        for (int q=0;q<32;q++) dst[q] = src[q];
    }
    for (int i = tid; i < 528; i += 256) hS[i] = 0.f;
    float creg = 0.f;
    __syncthreads();
    asm volatile("barrier.cluster.arrive.aligned;" ::: "memory");
    asm volatile("barrier.cluster.wait.aligned;" ::: "memory");

    unsigned int hS_addr;
    asm("{ .reg .u64 t; cvta.to.shared.u64 t, %1; cvt.u32.u64 %0, t; }" : "=r"(hS_addr) : "l"(hS));
    unsigned int peer = rank ^ 1u;
    unsigned int hS_peer;
    asm("mapa.shared::cluster.u32 %0, %1, %2;" : "=r"(hS_peer) : "r"(hS_addr), "r"(peer));

    int xrow = g*128 + U0 + ju;
    const ulonglong2* wrow = (const ulonglong2*)&ws[tid*132];
    const ulonglong2* h0p = (const ulonglong2*)&hS[0];
    const ulonglong2* h1p = (const ulonglong2*)&hS[132];
    const ulonglong2* h2p = (const ulonglong2*)&hS[264];
    const ulonglong2* h3p = (const ulonglong2*)&hS[396];
    int ub = tid >> 6, uju = tid & 63;

    for (int t=0; t<TSTEPS; t++){
        float x0 = d_xp[((b0+0)*TSTEPS + t)*512 + xrow];
        float x1 = d_xp[((b0+1)*TSTEPS + t)*512 + xrow];
        float x2 = d_xp[((b0+2)*TSTEPS + t)*512 + xrow];
        float x3 = d_xp[((b0+3)*TSTEPS + t)*512 + xrow];
        unsigned long long aL0=0,aH0=0,aL1=0,aH1=0,aL2=0,aH2=0,aL3=0,aH3=0;
        #pragma unroll 8
        for (int k4=0;k4<32;k4++){
            ulonglong2 w  = wrow[k4];
            ulonglong2 h0 = h0p[k4];
            ulonglong2 h1 = h1p[k4];
            ulonglong2 h2 = h2p[k4];
            ulonglong2 h3 = h3p[k4];
            ffma2(aL0, w.x, h0.x); ffma2(aH0, w.y, h0.y);
            ffma2(aL1, w.x, h1.x); ffma2(aH1, w.y, h1.y);
            ffma2(aL2, w.x, h2.x); ffma2(aH2, w.y, h2.y);
            ffma2(aL3, w.x, h3.x); ffma2(aH3, w.y, h3.y);
        }
        gbuf[tid*4+0] = pairsum(aL0) + pairsum(aH0) + x0;
        gbuf[tid*4+1] = pairsum(aL1) + pairsum(aH1) + x1;
        gbuf[tid*4+2] = pairsum(aL2) + pairsum(aH2) + x2;
        gbuf[tid*4+3] = pairsum(aL3) + pairsum(aH3) + x3;
        __syncthreads();
        float gi = gbuf[(0*64+uju)*4 + ub];
        float gf = gbuf[(1*64+uju)*4 + ub];
        float gg = gbuf[(2*64+uju)*4 + ub];
        float go = gbuf[(3*64+uju)*4 + ub];
        float cn = sigf(gf)*creg + sigf(gi)*tanhfa(gg);
        creg = cn;
        float hn = sigf(go)*tanhfa(cn);
        int hoff = ub*132 + U0 + uju;
        hS[hoff] = hn;
        asm volatile("st.shared::cluster.f32 [%0], %1;" :: "r"(hS_peer + hoff*4), "f"(hn) : "memory");
        if (t == TSTEPS-1) d_hT[(b0+ub)*128 + U0 + uju] = hn;
        asm volatile("barrier.cluster.arrive.aligned;" ::: "memory");
        asm volatile("barrier.cluster.wait.aligned;" ::: "memory");
    }
}

__global__ void k_fin(const float* __restrict__ fcW, const float* __restrict__ fcb,
                      float* __restrict__ out){
    __shared__ float r[128];
    int b = blockIdx.x, tid = threadIdx.x;
    float rep = d_gnum[b*128+tid] / (d_gden[b] + 1e-16f);
    float v = fcW[tid]*rep + fcW[128+tid]*d_hT[b*128+tid];
    r[tid] = v; __syncthreads();
    for (int off=64; off; off>>=1){
        if (tid < off) r[tid] += r[tid+off];
        __syncthreads();
    }
    if (tid == 0) out[b] = r[0] + fcb[0];
}

extern "C" void kernel_launch(void* const* d_in, const int* in_sizes, int n_in,
                              void* d_out, int out_size){
    const float* x      = (const float*)d_in[0];
    const int*   ei     = (const int*)  d_in[1];
    const int*   batch  = (const int*)  d_in[2];
    const float* quant  = (const float*)d_in[3];
    const float* gatW   = (const float*)d_in[4];
    const float* attS   = (const float*)d_in[5];
    const float* attD   = (const float*)d_in[6];
    const float* gatb   = (const float*)d_in[7];
    const float* g1     = (const float*)d_in[8];
    const float* b1     = (const float*)d_in[9];
    const float* m1     = (const float*)d_in[10];
    const float* v1     = (const float*)d_in[11];
    const float* gcnW   = (const float*)d_in[12];
    const float* gcnb   = (const float*)d_in[13];
    const float* g2     = (const float*)d_in[14];
    const float* b2     = (const float*)d_in[15];
    const float* m2     = (const float*)d_in[16];
    const float* v2     = (const float*)d_in[17];
    const float* gateW  = (const float*)d_in[18];
    const float* gateb  = (const float*)d_in[19];
    const float* Wih    = (const float*)d_in[20];
    const float* Whh    = (const float*)d_in[21];
    const float* bih    = (const float*)d_in[22];
    const float* bhh    = (const float*)d_in[23];
    const float* fcW    = (const float*)d_in[24];
    const float* fcb    = (const float*)d_in[25];
    float* out = (float*)d_out;

    cudaFuncSetAttribute(k_gemm, cudaFuncAttributeMaxDynamicSharedMemorySize, 84480);
    cudaFuncSetAttribute(k_lstmp, cudaFuncAttributeMaxDynamicSharedMemorySize, 141376);

    k_init<<<196,256>>>();
    k_count<<<3125,256>>>(ei);
    k_scan1<<<196,256>>>();
    k_scan2<<<1,256>>>();
    k_scan3<<<196,256>>>();
    k_prep<<<196,256>>>();
    k_gemm<<<296,256,84480>>>(x, gatW, attS, attD, 0);
    k_scatter<<<3125,256>>>(ei);
    k_gat<<<6250,256>>>(gatb, g1, b1, m1, v1);
    k_gemm<<<296,256,84480>>>(nullptr, gcnW, nullptr, nullptr, 1);
    k_gcn<<<6250,256>>>(batch, gcnb, g2, b2, m2, v2, gateW, gateb);
    k_xp<<<256,512>>>(quant, Wih, bih, bhh);
    k_lstmp<<<128,256,141376>>>(Whh);
    k_fin<<<256,128>>>(fcW, fcb, out);
    (void)in_sizes; (void)n_in; (void)out_size;
}

// round 5
// speedup vs baseline: 1.3140x; 1.3140x over previous
#include <cuda_runtime.h>

#define NN 50000
#define EE 800000
#define BBATCH 256
#define TSTEPS 50
#define FM 0xffffffffu

__device__ __align__(16) float d_xw[NN*128];
__device__ __align__(16) float d_h[NN*128];
__device__ __align__(16) float d_hw[NN*128];
__device__ __align__(16) float d_asrc[NN*4];
__device__ __align__(16) float d_adst[NN*4];
__device__ float d_dinv[NN];
__device__ int   d_deg[NN];
__device__ int   d_rowptr[NN+1];
__device__ int   d_cursor[NN];
__device__ int   d_colsrc[EE];
__device__ int   d_bsum[256], d_boff[256];
__device__ float d_gnum[BBATCH*128];
__device__ float d_gden[BBATCH];
__device__ __align__(16) float d_xp[BBATCH*TSTEPS*512];
__device__ float d_hT[BBATCH*128];

__device__ __forceinline__ float sigf(float x){ return __fdividef(1.f, 1.f + __expf(-x)); }
__device__ __forceinline__ float tanhfa(float x){ float e=__expf(2.f*x); return 1.f - __fdividef(2.f, e+1.f); }

__device__ __forceinline__ void ffma2(unsigned long long& d, unsigned long long a, unsigned long long b){
    asm("fma.rn.f32x2 %0, %1, %2, %0;" : "+l"(d) : "l"(a), "l"(b));
}
__device__ __forceinline__ float pairsum(unsigned long long v){
    float2 f; __builtin_memcpy(&f, &v, 8); return f.x + f.y;
}

__global__ void k_init(){
    int i = blockIdx.x*256 + threadIdx.x;
    if (i < NN) d_deg[i] = 0;
    if (i < BBATCH*128) d_gnum[i]=0.f;
    if (i < BBATCH) d_gden[i]=0.f;
}

__global__ void k_count(const int* __restrict__ ei){
    int i = blockIdx.x*256 + threadIdx.x;
    if (i < EE) atomicAdd(&d_deg[ei[EE+i]], 1);
}

__global__ void k_scan1(){
    __shared__ int s[256];
    int tid = threadIdx.x;
    int i = blockIdx.x*256 + tid;
    int v = (i < NN) ? d_deg[i] : 0;
    s[tid] = v; __syncthreads();
    for (int off=1; off<256; off<<=1){
        int t = (tid>=off) ? s[tid-off] : 0;
        __syncthreads(); s[tid] += t; __syncthreads();
    }
    if (i < NN) d_rowptr[i+1] = s[tid];
    if (tid == 255) d_bsum[blockIdx.x] = s[255];
}

__global__ void k_scan2(){
    __shared__ int s[256];
    int tid = threadIdx.x;
    int v = (tid < 196) ? d_bsum[tid] : 0;
    s[tid] = v; __syncthreads();
    for (int off=1; off<256; off<<=1){
        int t = (tid>=off) ? s[tid-off] : 0;
        __syncthreads(); s[tid] += t; __syncthreads();
    }
    if (tid < 196) d_boff[tid] = s[tid] - v;
}

__global__ void k_scan3(){
    int i = blockIdx.x*256 + threadIdx.x;
    if (i < NN) d_rowptr[i+1] += d_boff[blockIdx.x];
    if (i == 0) d_rowptr[0] = 0;
}

__global__ void k_prep(){
    int i = blockIdx.x*256 + threadIdx.x;
    if (i >= NN) return;
    int a = d_rowptr[i], b = d_rowptr[i+1];
    d_cursor[i] = a;
    d_dinv[i] = rsqrtf((float)(b - a + 1));
}

// position-only scatter (independent of GEMM)
__global__ void k_scatter(const int* __restrict__ ei){
    int i = blockIdx.x*256 + threadIdx.x;
    if (i >= EE) return;
    int s = ei[i], d = ei[EE+i];
    int pos = atomicAdd(&d_cursor[d], 1);
    d_colsrc[pos] = s;
}

// GEMM (R2 version): Y = X @ W; mode0: X=Xp, Y=d_xw + attention epilogue; mode1: X=d_h, Y=d_hw
__global__ void k_gemm(const float* __restrict__ Xp, const float* __restrict__ W,
                       const float* __restrict__ attS, const float* __restrict__ attD, int mode){
    extern __shared__ float sm[];
    float* Ws = sm;          // 128x128
    float* xs = sm + 16384;  // 16x128
    const float* X = mode ? d_h : Xp;
    float* Y = mode ? d_hw : d_xw;
    int tid = threadIdx.x, cg = tid & 31, rg = tid >> 5;
    for (int i = tid; i < 16384; i += 128) Ws[i] = W[i];
    float as0=0,as1=0,as2=0,as3=0, ad0=0,ad1=0,ad2=0,ad3=0;
    if (!mode){
        as0=attS[cg*4]; as1=attS[cg*4+1]; as2=attS[cg*4+2]; as3=attS[cg*4+3];
        ad0=attD[cg*4]; ad1=attD[cg*4+1]; ad2=attD[cg*4+2]; ad3=attD[cg*4+3];
    }
    __syncthreads();
    const float4* Ws4 = (const float4*)Ws;
    for (int chunk = blockIdx.x; chunk < NN/16; chunk += gridDim.x){
        int row0 = chunk*16;
        __syncthreads();
        for (int i = tid; i < 2048; i += 128){
            int r = i >> 7, k = i & 127;
            xs[i] = X[(row0+r)*128 + k];
        }
        __syncthreads();
        float a[4][4];
        #pragma unroll
        for (int r=0;r<4;r++){ a[r][0]=0;a[r][1]=0;a[r][2]=0;a[r][3]=0; }
        #pragma unroll 4
        for (int k=0;k<128;k++){
            float4 wv = Ws4[k*32 + cg];
            float x0 = xs[(rg*4+0)*128+k], x1 = xs[(rg*4+1)*128+k];
            float x2 = xs[(rg*4+2)*128+k], x3 = xs[(rg*4+3)*128+k];
            a[0][0]+=x0*wv.x; a[0][1]+=x0*wv.y; a[0][2]+=x0*wv.z; a[0][3]+=x0*wv.w;
            a[1][0]+=x1*wv.x; a[1][1]+=x1*wv.y; a[1][2]+=x1*wv.z; a[1][3]+=x1*wv.w;
            a[2][0]+=x2*wv.x; a[2][1]+=x2*wv.y; a[2][2]+=x2*wv.z; a[2][3]+=x2*wv.w;
            a[3][0]+=x3*wv.x; a[3][1]+=x3*wv.y; a[3][2]+=x3*wv.z; a[3][3]+=x3*wv.w;
        }
        #pragma unroll
        for (int r=0;r<4;r++){
            int grow = row0 + rg*4 + r;
            float4 o = make_float4(a[r][0],a[r][1],a[r][2],a[r][3]);
            *(float4*)&Y[grow*128 + cg*4] = o;
            if (!mode){
                float s = a[r][0]*as0 + a[r][1]*as1 + a[r][2]*as2 + a[r][3]*as3;
                float d = a[r][0]*ad0 + a[r][1]*ad1 + a[r][2]*ad2 + a[r][3]*ad3;
                #pragma unroll
                for (int off=4; off; off>>=1){
                    s += __shfl_xor_sync(FM, s, off);
                    d += __shfl_xor_sync(FM, d, off);
                }
                if ((cg & 7) == 0){
                    d_asrc[grow*4 + (cg>>3)] = s;
                    d_adst[grow*4 + (cg>>3)] = d;
                }
            }
        }
    }
}

__global__ void k_gat(const float* __restrict__ gatb,
                      const float* __restrict__ g1, const float* __restrict__ b1,
                      const float* __restrict__ m1, const float* __restrict__ v1){
    __shared__ float sc[128], sh[128], gb[128];
    int tid = threadIdx.x;
    if (tid < 128){
        float s = g1[tid]*rsqrtf(v1[tid]+1e-5f);
        sc[tid]=s; sh[tid]=b1[tid]-m1[tid]*s; gb[tid]=gatb[tid];
    }
    __syncthreads();
    int lane = tid & 31;
    int node = blockIdx.x*8 + (tid>>5);
    if (node >= NN) return;
    int begin = d_rowptr[node], end = d_rowptr[node+1];
    float4 adv = *(const float4*)&d_adst[node*4];
    float n0=0,n1=0,n2=0,n3=0;
    float dn0=0,dn1=0,dn2=0,dn3=0;
    for (int base = begin; base < end; base += 32){
        int idx = base + lane;
        int sl = 0; float4 exl = make_float4(0,0,0,0);
        if (idx < end){
            sl = d_colsrc[idx];
            float4 as = *(const float4*)&d_asrc[sl*4];
            float e0 = as.x+adv.x; e0 = e0>0.f? e0 : 0.2f*e0;
            float e1 = as.y+adv.y; e1 = e1>0.f? e1 : 0.2f*e1;
            float e2 = as.z+adv.z; e2 = e2>0.f? e2 : 0.2f*e2;
            float e3 = as.w+adv.w; e3 = e3>0.f? e3 : 0.2f*e3;
            exl = make_float4(__expf(e0),__expf(e1),__expf(e2),__expf(e3));
            dn0+=exl.x; dn1+=exl.y; dn2+=exl.z; dn3+=exl.w;
        }
        int cnt = min(32, end-base);
        for (int j=0;j<cnt;j++){
            int sj = __shfl_sync(FM, sl, j);
            float a0=__shfl_sync(FM,exl.x,j), a1=__shfl_sync(FM,exl.y,j);
            float a2=__shfl_sync(FM,exl.z,j), a3=__shfl_sync(FM,exl.w,j);
            float aj = lane<8? a0 : lane<16? a1 : lane<24? a2 : a3;
            float4 xv = *(const float4*)&d_xw[sj*128 + lane*4];
            n0 += xv.x*aj; n1 += xv.y*aj; n2 += xv.z*aj; n3 += xv.w*aj;
        }
    }
    #pragma unroll
    for (int off=16; off; off>>=1){
        dn0 += __shfl_xor_sync(FM,dn0,off); dn1 += __shfl_xor_sync(FM,dn1,off);
        dn2 += __shfl_xor_sync(FM,dn2,off); dn3 += __shfl_xor_sync(FM,dn3,off);
    }
    float4 as = *(const float4*)&d_asrc[node*4];
    float e0=as.x+adv.x; e0=e0>0.f?e0:0.2f*e0; float x0=__expf(e0);
    float e1=as.y+adv.y; e1=e1>0.f?e1:0.2f*e1; float x1=__expf(e1);
    float e2=as.z+adv.z; e2=e2>0.f?e2:0.2f*e2; float x2=__expf(e2);
    float e3=as.w+adv.w; e3=e3>0.f?e3:0.2f*e3; float x3=__expf(e3);
    dn0+=x0; dn1+=x1; dn2+=x2; dn3+=x3;
    float4 xv = *(const float4*)&d_xw[node*128 + lane*4];
    float aself = lane<8? x0 : lane<16? x1 : lane<24? x2 : x3;
    n0 += xv.x*aself; n1 += xv.y*aself; n2 += xv.z*aself; n3 += xv.w*aself;
    float hd = lane<8? dn0 : lane<16? dn1 : lane<24? dn2 : dn3;
    float inv = 1.0f/(hd + 1e-16f);
    int col = lane*4;
    float o0 = n0*inv + gb[col];   o0 = o0>0.f? o0 : expm1f(o0); o0 = o0*sc[col]+sh[col];
    float o1 = n1*inv + gb[col+1]; o1 = o1>0.f? o1 : expm1f(o1); o1 = o1*sc[col+1]+sh[col+1];
    float o2 = n2*inv + gb[col+2]; o2 = o2>0.f? o2 : expm1f(o2); o2 = o2*sc[col+2]+sh[col+2];
    float o3 = n3*inv + gb[col+3]; o3 = o3>0.f? o3 : expm1f(o3); o3 = o3*sc[col+3]+sh[col+3];
    *(float4*)&d_h[node*128 + col] = make_float4(o0,o1,o2,o3);
}

__global__ void k_gcn(const int* __restrict__ batch,
                      const float* __restrict__ gcnb,
                      const float* __restrict__ g2, const float* __restrict__ b2,
                      const float* __restrict__ m2, const float* __restrict__ v2,
                      const float* __restrict__ gateW, const float* __restrict__ gateb){
    __shared__ float sc[128], sh[128], gb[128], gw[128];
    int tid = threadIdx.x;
    if (tid < 128){
        float s = g2[tid]*rsqrtf(v2[tid]+1e-5f);
        sc[tid]=s; sh[tid]=b2[tid]-m2[tid]*s; gb[tid]=gcnb[tid]; gw[tid]=gateW[tid];
    }
    __syncthreads();
    int lane = tid & 31;
    int node = blockIdx.x*8 + (tid>>5);
    if (node >= NN) return;
    int begin = d_rowptr[node], end = d_rowptr[node+1];
    float did = d_dinv[node];
    float a0=0,a1=0,a2=0,a3=0;
    for (int base = begin; base < end; base += 32){
        int idx = base + lane;
        int sl = 0; float dsl = 0.f;
        if (idx < end){ sl = d_colsrc[idx]; dsl = d_dinv[sl]; }
        int cnt = min(32, end-base);
        for (int j=0;j<cnt;j++){
            int sj = __shfl_sync(FM, sl, j);
            float ds = __shfl_sync(FM, dsl, j);
            float4 hv = *(const float4*)&d_hw[sj*128 + lane*4];
            a0 += hv.x*ds; a1 += hv.y*ds; a2 += hv.z*ds; a3 += hv.w*ds;
        }
    }
    int col = lane*4;
    float4 sv = *(const float4*)&d_hw[node*128 + col];
    float h0 = did*(a0 + did*sv.x) + gb[col];
    float h1 = did*(a1 + did*sv.y) + gb[col+1];
    float h2v = did*(a2 + did*sv.z) + gb[col+2];
    float h3 = did*(a3 + did*sv.w) + gb[col+3];
    h0 = h0>0.f? h0 : expm1f(h0); h0 = h0*sc[col]+sh[col];
    h1 = h1>0.f? h1 : expm1f(h1); h1 = h1*sc[col+1]+sh[col+1];
    h2v = h2v>0.f? h2v : expm1f(h2v); h2v = h2v*sc[col+2]+sh[col+2];
    h3 = h3>0.f? h3 : expm1f(h3); h3 = h3*sc[col+3]+sh[col+3];
    float g = h0*gw[col] + h1*gw[col+1] + h2v*gw[col+2] + h3*gw[col+3];
    #pragma unroll
    for (int off=16; off; off>>=1) g += __shfl_xor_sync(FM, g, off);
    g += gateb[0];
    float p = __expf(g);
    int b = batch[node];
    if (lane == 0) atomicAdd(&d_gden[b], p);
    atomicAdd(&d_gnum[b*128+col],   p*h0);
    atomicAdd(&d_gnum[b*128+col+1], p*h1);
    atomicAdd(&d_gnum[b*128+col+2], p*h2v);
    atomicAdd(&d_gnum[b*128+col+3], p*h3);
}

__global__ void k_xp(const float* __restrict__ quant, const float* __restrict__ Wih,
                     const float* __restrict__ bih, const float* __restrict__ bhh){
    __shared__ float qS[TSTEPS*32];
    int b = blockIdx.x, g = threadIdx.x;
    for (int i = g; i < TSTEPS*32; i += 512) qS[i] = quant[b*TSTEPS*32 + i];
    float4 wr[8];
    #pragma unroll
    for (int q=0;q<8;q++) wr[q] = *(const float4*)&Wih[g*32 + q*4];
    float bias = bih[g] + bhh[g];
    __syncthreads();
    const float4* qS4 = (const float4*)qS;
    for (int t=0; t<TSTEPS; t++){
        float acc = bias;
        #pragma unroll
        for (int q=0;q<8;q++){
            float4 xv = qS4[t*8+q];
            acc += wr[q].x*xv.x + wr[q].y*xv.y + wr[q].z*xv.z + wr[q].w*xv.w;
        }
        d_xp[(b*TSTEPS + t)*512 + g] = acc;
    }
}

__global__ void __cluster_dims__(2,1,1) k_lstmp(const float* __restrict__ Whh){
    extern __shared__ float sm[];
    float* ws   = sm;            // 256 rows x 132 (padded)
    float* hS   = sm + 33792;    // 4 x 132
    float* gbuf = sm + 34320;    // 256 x 4
    int tid = threadIdx.x;
    unsigned int rank;
    asm("mov.u32 %0, %%cluster_ctarank;" : "=r"(rank));
    int U0 = (int)rank * 64;
    int b0 = (blockIdx.x >> 1) * 4;
    int g  = tid >> 6, ju = tid & 63;

    {
        const float4* src = (const float4*)&Whh[(g*128 + U0 + ju)*128];
        float4* dst = (float4*)&ws[tid*132];
        #pragma unroll
        for (int q=0;q<32;q++) dst[q] = src[q];
    }
    for (int i = tid; i < 528; i += 256) hS[i] = 0.f;
    float creg = 0.f;
    __syncthreads();
    asm volatile("barrier.cluster.arrive.aligned;" ::: "memory");
    asm volatile("barrier.cluster.wait.aligned;" ::: "memory");

    unsigned int hS_addr;
    asm("{ .reg .u64 t; cvta.to.shared.u64 t, %1; cvt.u32.u64 %0, t; }" : "=r"(hS_addr) : "l"(hS));
    unsigned int peer = rank ^ 1u;
    unsigned int hS_peer;
    asm("mapa.shared::cluster.u32 %0, %1, %2;" : "=r"(hS_peer) : "r"(hS_addr), "r"(peer));

    int xrow = g*128 + U0 + ju;
    const ulonglong2* wrow = (const ulonglong2*)&ws[tid*132];
    const ulonglong2* h0p = (const ulonglong2*)&hS[0];
    const ulonglong2* h1p = (const ulonglong2*)&hS[132];
    const ulonglong2* h2p = (const ulonglong2*)&hS[264];
    const ulonglong2* h3p = (const ulonglong2*)&hS[396];
    int ub = tid >> 6, uju = tid & 63;

    for (int t=0; t<TSTEPS; t++){
        float x0 = d_xp[((b0+0)*TSTEPS + t)*512 + xrow];
        float x1 = d_xp[((b0+1)*TSTEPS + t)*512 + xrow];
        float x2 = d_xp[((b0+2)*TSTEPS + t)*512 + xrow];
        float x3 = d_xp[((b0+3)*TSTEPS + t)*512 + xrow];
        unsigned long long aL0=0,aH0=0,aL1=0,aH1=0,aL2=0,aH2=0,aL3=0,aH3=0;
        #pragma unroll 8
        for (int k4=0;k4<32;k4++){
            ulonglong2 w  = wrow[k4];
            ulonglong2 h0 = h0p[k4];
            ulonglong2 h1 = h1p[k4];
            ulonglong2 h2 = h2p[k4];
            ulonglong2 h3 = h3p[k4];
            ffma2(aL0, w.x, h0.x); ffma2(aH0, w.y, h0.y);
            ffma2(aL1, w.x, h1.x); ffma2(aH1, w.y, h1.y);
            ffma2(aL2, w.x, h2.x); ffma2(aH2, w.y, h2.y);
            ffma2(aL3, w.x, h3.x); ffma2(aH3, w.y, h3.y);
        }
        gbuf[tid*4+0] = pairsum(aL0) + pairsum(aH0) + x0;
        gbuf[tid*4+1] = pairsum(aL1) + pairsum(aH1) + x1;
        gbuf[tid*4+2] = pairsum(aL2) + pairsum(aH2) + x2;
        gbuf[tid*4+3] = pairsum(aL3) + pairsum(aH3) + x3;
        __syncthreads();
        float gi = gbuf[(0*64+uju)*4 + ub];
        float gf = gbuf[(1*64+uju)*4 + ub];
        float gg = gbuf[(2*64+uju)*4 + ub];
        float go = gbuf[(3*64+uju)*4 + ub];
        float cn = sigf(gf)*creg + sigf(gi)*tanhfa(gg);
        creg = cn;
        float hn = sigf(go)*tanhfa(cn);
        int hoff = ub*132 + U0 + uju;
        hS[hoff] = hn;
        asm volatile("st.shared::cluster.f32 [%0], %1;" :: "r"(hS_peer + hoff*4), "f"(hn) : "memory");
        if (t == TSTEPS-1) d_hT[(b0+ub)*128 + U0 + uju] = hn;
        asm volatile("barrier.cluster.arrive.aligned;" ::: "memory");
        asm volatile("barrier.cluster.wait.aligned;" ::: "memory");
    }
}

__global__ void k_fin(const float* __restrict__ fcW, const float* __restrict__ fcb,
                      float* __restrict__ out){
    __shared__ float r[128];
    int b = blockIdx.x, tid = threadIdx.x;
    float rep = d_gnum[b*128+tid] / (d_gden[b] + 1e-16f);
    float v = fcW[tid]*rep + fcW[128+tid]*d_hT[b*128+tid];
    r[tid] = v; __syncthreads();
    for (int off=64; off; off>>=1){
        if (tid < off) r[tid] += r[tid+off];
        __syncthreads();
    }
    if (tid == 0) out[b] = r[0] + fcb[0];
}

extern "C" void kernel_launch(void* const* d_in, const int* in_sizes, int n_in,
                              void* d_out, int out_size){
    const float* x      = (const float*)d_in[0];
    const int*   ei     = (const int*)  d_in[1];
    const int*   batch  = (const int*)  d_in[2];
    const float* quant  = (const float*)d_in[3];
    const float* gatW   = (const float*)d_in[4];
    const float* attS   = (const float*)d_in[5];
    const float* attD   = (const float*)d_in[6];
    const float* gatb   = (const float*)d_in[7];
    const float* g1     = (const float*)d_in[8];
    const float* b1     = (const float*)d_in[9];
    const float* m1     = (const float*)d_in[10];
    const float* v1     = (const float*)d_in[11];
    const float* gcnW   = (const float*)d_in[12];
    const float* gcnb   = (const float*)d_in[13];
    const float* g2     = (const float*)d_in[14];
    const float* b2     = (const float*)d_in[15];
    const float* m2     = (const float*)d_in[16];
    const float* v2     = (const float*)d_in[17];
    const float* gateW  = (const float*)d_in[18];
    const float* gateb  = (const float*)d_in[19];
    const float* Wih    = (const float*)d_in[20];
    const float* Whh    = (const float*)d_in[21];
    const float* bih    = (const float*)d_in[22];
    const float* bhh    = (const float*)d_in[23];
    const float* fcW    = (const float*)d_in[24];
    const float* fcb    = (const float*)d_in[25];
    float* out = (float*)d_out;

    cudaFuncSetAttribute(k_gemm, cudaFuncAttributeMaxDynamicSharedMemorySize, 73728);
    cudaFuncSetAttribute(k_lstmp, cudaFuncAttributeMaxDynamicSharedMemorySize, 141376);

    cudaStream_t sA, sB;
    cudaStreamCreateWithFlags(&sA, cudaStreamNonBlocking);
    cudaStreamCreateWithFlags(&sB, cudaStreamNonBlocking);
    cudaEvent_t eFork, eCsr, eG1, eLstm;
    cudaEventCreateWithFlags(&eFork, cudaEventDisableTiming);
    cudaEventCreateWithFlags(&eCsr,  cudaEventDisableTiming);
    cudaEventCreateWithFlags(&eG1,   cudaEventDisableTiming);
    cudaEventCreateWithFlags(&eLstm, cudaEventDisableTiming);

    // fork point on the capture (default) stream
    cudaEventRecord(eFork, 0);

    // side stream A: CSR build (independent of GEMM1)
    cudaStreamWaitEvent(sA, eFork, 0);
    k_init<<<196,256,0,sA>>>();
    k_count<<<3125,256,0,sA>>>(ei);
    k_scan1<<<196,256,0,sA>>>();
    k_scan2<<<1,256,0,sA>>>();
    k_scan3<<<196,256,0,sA>>>();
    k_prep<<<196,256,0,sA>>>();
    k_scatter<<<3125,256,0,sA>>>(ei);
    cudaEventRecord(eCsr, sA);

    // main stream: GEMM1 concurrent with CSR build
    k_gemm<<<444,128,73728>>>(x, gatW, attS, attD, 0);
    cudaEventRecord(eG1, 0);

    // side stream B: LSTM branch, started after GEMM1 so it overlaps gat/gemm2/gcn
    cudaStreamWaitEvent(sB, eG1, 0);
    k_xp<<<256,512,0,sB>>>(quant, Wih, bih, bhh);
    k_lstmp<<<128,256,141376,sB>>>(Whh);
    cudaEventRecord(eLstm, sB);

    // main stream: join CSR, then aggregation chain
    cudaStreamWaitEvent(0, eCsr, 0);
    k_gat<<<6250,256>>>(gatb, g1, b1, m1, v1);
    k_gemm<<<444,128,73728>>>(nullptr, gcnW, nullptr, nullptr, 1);
    k_gcn<<<6250,256>>>(batch, gcnb, g2, b2, m2, v2, gateW, gateb);

    // join LSTM, finalize
    cudaStreamWaitEvent(0, eLstm, 0);
    k_fin<<<256,128>>>(fcW, fcb, out);

    cudaStreamDestroy(sA);
    cudaStreamDestroy(sB);
    cudaEventDestroy(eFork);
    cudaEventDestroy(eCsr);
    cudaEventDestroy(eG1);
    cudaEventDestroy(eLstm);
    (void)in_sizes; (void)n_in; (void)out_size;
}

// round 8
// speedup vs baseline: 1.4586x; 1.1101x over previous
#include <cuda_runtime.h>

#define NN 50000
#define EE 800000
#define BBATCH 256
#define TSTEPS 50
#define FM 0xffffffffu

__device__ __align__(16) float d_xw[NN*128];
__device__ __align__(16) float d_h[NN*128];
__device__ __align__(16) float d_hw[NN*128];
__device__ __align__(16) float d_asrc[NN*4];
__device__ __align__(16) float d_adst[NN*4];
__device__ float d_dinv[NN];
__device__ int   d_deg[NN];
__device__ int   d_rowptr[NN+1];
__device__ int   d_cursor[NN];
__device__ int   d_colsrc[EE];
__device__ int   d_bsum[256], d_boff[256];
__device__ float d_gnum[BBATCH*128];
__device__ float d_gden[BBATCH];
__device__ __align__(16) float d_xp[BBATCH*TSTEPS*512];
__device__ float d_hT[BBATCH*128];

__device__ __forceinline__ float sigf(float x){ return __fdividef(1.f, 1.f + __expf(-x)); }
__device__ __forceinline__ float tanhfa(float x){ float e=__expf(2.f*x); return 1.f - __fdividef(2.f, e+1.f); }

__device__ __forceinline__ void ffma2(unsigned long long& d, unsigned long long a, unsigned long long b){
    asm("fma.rn.f32x2 %0, %1, %2, %0;" : "+l"(d) : "l"(a), "l"(b));
}
__device__ __forceinline__ float pairsum(unsigned long long v){
    float2 f; __builtin_memcpy(&f, &v, 8); return f.x + f.y;
}

__global__ void k_init(){
    int i = blockIdx.x*256 + threadIdx.x;
    if (i < NN) d_deg[i] = 0;
    if (i < BBATCH*128) d_gnum[i]=0.f;
    if (i < BBATCH) d_gden[i]=0.f;
}

__global__ void k_count(const int* __restrict__ ei){
    int i = blockIdx.x*256 + threadIdx.x;
    if (i < EE) atomicAdd(&d_deg[ei[EE+i]], 1);
}

__global__ void k_scan1(){
    __shared__ int s[256];
    int tid = threadIdx.x;
    int i = blockIdx.x*256 + tid;
    int v = (i < NN) ? d_deg[i] : 0;
    s[tid] = v; __syncthreads();
    for (int off=1; off<256; off<<=1){
        int t = (tid>=off) ? s[tid-off] : 0;
        __syncthreads(); s[tid] += t; __syncthreads();
    }
    if (i < NN) d_rowptr[i+1] = s[tid];
    if (tid == 255) d_bsum[blockIdx.x] = s[255];
}

__global__ void k_scan2(){
    __shared__ int s[256];
    int tid = threadIdx.x;
    int v = (tid < 196) ? d_bsum[tid] : 0;
    s[tid] = v; __syncthreads();
    for (int off=1; off<256; off<<=1){
        int t = (tid>=off) ? s[tid-off] : 0;
        __syncthreads(); s[tid] += t; __syncthreads();
    }
    if (tid < 196) d_boff[tid] = s[tid] - v;
}

__global__ void k_scan3(){
    int i = blockIdx.x*256 + threadIdx.x;
    if (i < NN) d_rowptr[i+1] += d_boff[blockIdx.x];
    if (i == 0) d_rowptr[0] = 0;
}

__global__ void k_prep(){
    int i = blockIdx.x*256 + threadIdx.x;
    if (i >= NN) return;
    int a = d_rowptr[i], b = d_rowptr[i+1];
    d_cursor[i] = a;
    d_dinv[i] = rsqrtf((float)(b - a + 1));
}

__global__ void k_scatter(const int* __restrict__ ei){
    int i = blockIdx.x*256 + threadIdx.x;
    if (i >= EE) return;
    int s = ei[i], d = ei[EE+i];
    int pos = atomicAdd(&d_cursor[d], 1);
    d_colsrc[pos] = s;
}

// GEMM: Y = X @ W; mode0: X=Xp, Y=d_xw + attention epilogue; mode1: X=d_h, Y=d_hw
__global__ void k_gemm(const float* __restrict__ Xp, const float* __restrict__ W,
                       const float* __restrict__ attS, const float* __restrict__ attD, int mode){
    extern __shared__ float sm[];
    float* Ws = sm;          // 128x128
    float* xs = sm + 16384;  // 16x128
    const float* X = mode ? d_h : Xp;
    float* Y = mode ? d_hw : d_xw;
    int tid = threadIdx.x, cg = tid & 31, rg = tid >> 5;
    for (int i = tid; i < 16384; i += 128) Ws[i] = W[i];
    float as0=0,as1=0,as2=0,as3=0, ad0=0,ad1=0,ad2=0,ad3=0;
    if (!mode){
        as0=attS[cg*4]; as1=attS[cg*4+1]; as2=attS[cg*4+2]; as3=attS[cg*4+3];
        ad0=attD[cg*4]; ad1=attD[cg*4+1]; ad2=attD[cg*4+2]; ad3=attD[cg*4+3];
    }
    __syncthreads();
    const float4* Ws4 = (const float4*)Ws;
    for (int chunk = blockIdx.x; chunk < NN/16; chunk += gridDim.x){
        int row0 = chunk*16;
        __syncthreads();
        for (int i = tid; i < 2048; i += 128){
            int r = i >> 7, k = i & 127;
            xs[i] = X[(row0+r)*128 + k];
        }
        __syncthreads();
        float a[4][4];
        #pragma unroll
        for (int r=0;r<4;r++){ a[r][0]=0;a[r][1]=0;a[r][2]=0;a[r][3]=0; }
        #pragma unroll 4
        for (int k=0;k<128;k++){
            float4 wv = Ws4[k*32 + cg];
            float x0 = xs[(rg*4+0)*128+k], x1 = xs[(rg*4+1)*128+k];
            float x2 = xs[(rg*4+2)*128+k], x3 = xs[(rg*4+3)*128+k];
            a[0][0]+=x0*wv.x; a[0][1]+=x0*wv.y; a[0][2]+=x0*wv.z; a[0][3]+=x0*wv.w;
            a[1][0]+=x1*wv.x; a[1][1]+=x1*wv.y; a[1][2]+=x1*wv.z; a[1][3]+=x1*wv.w;
            a[2][0]+=x2*wv.x; a[2][1]+=x2*wv.y; a[2][2]+=x2*wv.z; a[2][3]+=x2*wv.w;
            a[3][0]+=x3*wv.x; a[3][1]+=x3*wv.y; a[3][2]+=x3*wv.z; a[3][3]+=x3*wv.w;
        }
        #pragma unroll
        for (int r=0;r<4;r++){
            int grow = row0 + rg*4 + r;
            float4 o = make_float4(a[r][0],a[r][1],a[r][2],a[r][3]);
            *(float4*)&Y[grow*128 + cg*4] = o;
            if (!mode){
                float s = a[r][0]*as0 + a[r][1]*as1 + a[r][2]*as2 + a[r][3]*as3;
                float d = a[r][0]*ad0 + a[r][1]*ad1 + a[r][2]*ad2 + a[r][3]*ad3;
                #pragma unroll
                for (int off=4; off; off>>=1){
                    s += __shfl_xor_sync(FM, s, off);
                    d += __shfl_xor_sync(FM, d, off);
                }
                if ((cg & 7) == 0){
                    d_asrc[grow*4 + (cg>>3)] = s;
                    d_adst[grow*4 + (cg>>3)] = d;
                }
            }
        }
    }
}

__global__ void k_gat(const float* __restrict__ gatb,
                      const float* __restrict__ g1, const float* __restrict__ b1,
                      const float* __restrict__ m1, const float* __restrict__ v1){
    __shared__ float sc[128], sh[128], gb[128];
    int tid = threadIdx.x;
    if (tid < 128){
        float s = g1[tid]*rsqrtf(v1[tid]+1e-5f);
        sc[tid]=s; sh[tid]=b1[tid]-m1[tid]*s; gb[tid]=gatb[tid];
    }
    __syncthreads();
    int lane = tid & 31;
    int node = blockIdx.x*8 + (tid>>5);
    if (node >= NN) return;
    int begin = d_rowptr[node], end = d_rowptr[node+1];
    float4 adv = *(const float4*)&d_adst[node*4];
    float n0=0,n1=0,n2=0,n3=0;
    float dn0=0,dn1=0,dn2=0,dn3=0;
    for (int base = begin; base < end; base += 32){
        int idx = base + lane;
        int sl = 0; float4 exl = make_float4(0,0,0,0);
        if (idx < end){
            sl = d_colsrc[idx];
            float4 as = *(const float4*)&d_asrc[sl*4];
            float e0 = as.x+adv.x; e0 = e0>0.f? e0 : 0.2f*e0;
            float e1 = as.y+adv.y; e1 = e1>0.f? e1 : 0.2f*e1;
            float e2 = as.z+adv.z; e2 = e2>0.f? e2 : 0.2f*e2;
            float e3 = as.w+adv.w; e3 = e3>0.f? e3 : 0.2f*e3;
            exl = make_float4(__expf(e0),__expf(e1),__expf(e2),__expf(e3));
            dn0+=exl.x; dn1+=exl.y; dn2+=exl.z; dn3+=exl.w;
        }
        int cnt = min(32, end-base);
        for (int j=0;j<cnt;j++){
            int sj = __shfl_sync(FM, sl, j);
            float a0=__shfl_sync(FM,exl.x,j), a1=__shfl_sync(FM,exl.y,j);
            float a2=__shfl_sync(FM,exl.z,j), a3=__shfl_sync(FM,exl.w,j);
            float aj = lane<8? a0 : lane<16? a1 : lane<24? a2 : a3;
            float4 xv = *(const float4*)&d_xw[sj*128 + lane*4];
            n0 += xv.x*aj; n1 += xv.y*aj; n2 += xv.z*aj; n3 += xv.w*aj;
        }
    }
    #pragma unroll
    for (int off=16; off; off>>=1){
        dn0 += __shfl_xor_sync(FM,dn0,off); dn1 += __shfl_xor_sync(FM,dn1,off);
        dn2 += __shfl_xor_sync(FM,dn2,off); dn3 += __shfl_xor_sync(FM,dn3,off);
    }
    float4 as = *(const float4*)&d_asrc[node*4];
    float e0=as.x+adv.x; e0=e0>0.f?e0:0.2f*e0; float x0=__expf(e0);
    float e1=as.y+adv.y; e1=e1>0.f?e1:0.2f*e1; float x1=__expf(e1);
    float e2=as.z+adv.z; e2=e2>0.f?e2:0.2f*e2; float x2=__expf(e2);
    float e3=as.w+adv.w; e3=e3>0.f?e3:0.2f*e3; float x3=__expf(e3);
    dn0+=x0; dn1+=x1; dn2+=x2; dn3+=x3;
    float4 xv = *(const float4*)&d_xw[node*128 + lane*4];
    float aself = lane<8? x0 : lane<16? x1 : lane<24? x2 : x3;
    n0 += xv.x*aself; n1 += xv.y*aself; n2 += xv.z*aself; n3 += xv.w*aself;
    float hd = lane<8? dn0 : lane<16? dn1 : lane<24? dn2 : dn3;
    float inv = 1.0f/(hd + 1e-16f);
    int col = lane*4;
    float o0 = n0*inv + gb[col];   o0 = o0>0.f? o0 : expm1f(o0); o0 = o0*sc[col]+sh[col];
    float o1 = n1*inv + gb[col+1]; o1 = o1>0.f? o1 : expm1f(o1); o1 = o1*sc[col+1]+sh[col+1];
    float o2 = n2*inv + gb[col+2]; o2 = o2>0.f? o2 : expm1f(o2); o2 = o2*sc[col+2]+sh[col+2];
    float o3 = n3*inv + gb[col+3]; o3 = o3>0.f? o3 : expm1f(o3); o3 = o3*sc[col+3]+sh[col+3];
    *(float4*)&d_h[node*128 + col] = make_float4(o0,o1,o2,o3);
}

__global__ void k_gcn(const int* __restrict__ batch,
                      const float* __restrict__ gcnb,
                      const float* __restrict__ g2, const float* __restrict__ b2,
                      const float* __restrict__ m2, const float* __restrict__ v2,
                      const float* __restrict__ gateW, const float* __restrict__ gateb){
    __shared__ float sc[128], sh[128], gb[128], gw[128];
    int tid = threadIdx.x;
    if (tid < 128){
        float s = g2[tid]*rsqrtf(v2[tid]+1e-5f);
        sc[tid]=s; sh[tid]=b2[tid]-m2[tid]*s; gb[tid]=gcnb[tid]; gw[tid]=gateW[tid];
    }
    __syncthreads();
    int lane = tid & 31;
    int node = blockIdx.x*8 + (tid>>5);
    if (node >= NN) return;
    int begin = d_rowptr[node], end = d_rowptr[node+1];
    float did = d_dinv[node];
    float a0=0,a1=0,a2=0,a3=0;
    for (int base = begin; base < end; base += 32){
        int idx = base + lane;
        int sl = 0; float dsl = 0.f;
        if (idx < end){ sl = d_colsrc[idx]; dsl = d_dinv[sl]; }
        int cnt = min(32, end-base);
        for (int j=0;j<cnt;j++){
            int sj = __shfl_sync(FM, sl, j);
            float ds = __shfl_sync(FM, dsl, j);
            float4 hv = *(const float4*)&d_hw[sj*128 + lane*4];
            a0 += hv.x*ds; a1 += hv.y*ds; a2 += hv.z*ds; a3 += hv.w*ds;
        }
    }
    int col = lane*4;
    float4 sv = *(const float4*)&d_hw[node*128 + col];
    float h0 = did*(a0 + did*sv.x) + gb[col];
    float h1 = did*(a1 + did*sv.y) + gb[col+1];
    float h2v = did*(a2 + did*sv.z) + gb[col+2];
    float h3 = did*(a3 + did*sv.w) + gb[col+3];
    h0 = h0>0.f? h0 : expm1f(h0); h0 = h0*sc[col]+sh[col];
    h1 = h1>0.f? h1 : expm1f(h1); h1 = h1*sc[col+1]+sh[col+1];
    h2v = h2v>0.f? h2v : expm1f(h2v); h2v = h2v*sc[col+2]+sh[col+2];
    h3 = h3>0.f? h3 : expm1f(h3); h3 = h3*sc[col+3]+sh[col+3];
    float g = h0*gw[col] + h1*gw[col+1] + h2v*gw[col+2] + h3*gw[col+3];
    #pragma unroll
    for (int off=16; off; off>>=1) g += __shfl_xor_sync(FM, g, off);
    g += gateb[0];
    float p = __expf(g);
    int b = batch[node];
    if (lane == 0) atomicAdd(&d_gden[b], p);
    atomicAdd(&d_gnum[b*128+col],   p*h0);
    atomicAdd(&d_gnum[b*128+col+1], p*h1);
    atomicAdd(&d_gnum[b*128+col+2], p*h2v);
    atomicAdd(&d_gnum[b*128+col+3], p*h3);
}

__global__ void k_xp(const float* __restrict__ quant, const float* __restrict__ Wih,
                     const float* __restrict__ bih, const float* __restrict__ bhh){
    __shared__ float qS[TSTEPS*32];
    int b = blockIdx.x, g = threadIdx.x;
    for (int i = g; i < TSTEPS*32; i += 512) qS[i] = quant[b*TSTEPS*32 + i];
    float4 wr[8];
    #pragma unroll
    for (int q=0;q<8;q++) wr[q] = *(const float4*)&Wih[g*32 + q*4];
    float bias = bih[g] + bhh[g];
    __syncthreads();
    const float4* qS4 = (const float4*)qS;
    for (int t=0; t<TSTEPS; t++){
        float acc = bias;
        #pragma unroll
        for (int q=0;q<8;q++){
            float4 xv = qS4[t*8+q];
            acc += wr[q].x*xv.x + wr[q].y*xv.y + wr[q].z*xv.z + wr[q].w*xv.w;
        }
        d_xp[(b*TSTEPS + t)*512 + g] = acc;
    }
}

// LSTM v3: weights in registers (64 x f32x2 per thread), h batch/k-pair transposed
// in 2KB smem, broadcast loads only. Cluster-2 splits the 128 units; DSMEM exchange.
__global__ void __cluster_dims__(2,1,1) __launch_bounds__(256,1)
k_lstmp(const float* __restrict__ Whh){
    __shared__ __align__(16) float hps[512];   // [k2][8]: b0k0,b0k1,b1k0,b1k1,b2k0,b2k1,b3k0,b3k1
    __shared__ float gbuf[1024];
    int tid = threadIdx.x;
    unsigned int rank;
    asm("mov.u32 %0, %%cluster_ctarank;" : "=r"(rank));
    int U0 = (int)rank * 64;
    int b0 = (blockIdx.x >> 1) * 4;
    int g = tid >> 6, ju = tid & 63;
    int row = g*128 + U0 + ju;

    union { unsigned long long u[64]; float4 v[32]; } W;
    {
        const float4* row4 = (const float4*)&Whh[row*128];
        #pragma unroll
        for (int j=0;j<32;j++) W.v[j] = row4[j];
    }
    for (int i = tid; i < 512; i += 256) hps[i] = 0.f;
    float creg = 0.f;
    __syncthreads();
    asm volatile("barrier.cluster.arrive.aligned;" ::: "memory");
    asm volatile("barrier.cluster.wait.aligned;" ::: "memory");

    unsigned int hps_addr;
    asm("{ .reg .u64 t; cvta.to.shared.u64 t, %1; cvt.u32.u64 %0, t; }" : "=r"(hps_addr) : "l"(hps));
    unsigned int peer = rank ^ 1u;
    unsigned int hps_peer;
    asm("mapa.shared::cluster.u32 %0, %1, %2;" : "=r"(hps_peer) : "r"(hps_addr), "r"(peer));

    const ulonglong2* hp4 = (const ulonglong2*)hps;
    int ub = tid >> 6, uju = tid & 63;
    int hk = U0 + uju;                               // unit position in h
    int woff = (hk>>1)*8 + (ub>>1)*4 + (ub&1)*2 + (hk&1);  // float offset in hps

    for (int t=0; t<TSTEPS; t++){
        float x0 = d_xp[((b0+0)*TSTEPS + t)*512 + row];
        float x1 = d_xp[((b0+1)*TSTEPS + t)*512 + row];
        float x2 = d_xp[((b0+2)*TSTEPS + t)*512 + row];
        float x3 = d_xp[((b0+3)*TSTEPS + t)*512 + row];
        unsigned long long a0=0,a1=0,a2=0,a3=0;
        #pragma unroll
        for (int k2=0;k2<64;k2++){
            ulonglong2 hA = hp4[2*k2];
            ulonglong2 hB = hp4[2*k2+1];
            ffma2(a0, W.u[k2], hA.x);
            ffma2(a1, W.u[k2], hA.y);
            ffma2(a2, W.u[k2], hB.x);
            ffma2(a3, W.u[k2], hB.y);
        }
        ((float4*)gbuf)[tid] = make_float4(pairsum(a0)+x0, pairsum(a1)+x1,
                                           pairsum(a2)+x2, pairsum(a3)+x3);
        __syncthreads();
        float gi = gbuf[(0*64+uju)*4 + ub];
        float gf = gbuf[(1*64+uju)*4 + ub];
        float gg = gbuf[(2*64+uju)*4 + ub];
        float go = gbuf[(3*64+uju)*4 + ub];
        float cn = sigf(gf)*creg + sigf(gi)*tanhfa(gg);
        creg = cn;
        float hn = sigf(go)*tanhfa(cn);
        hps[woff] = hn;
        asm volatile("st.shared::cluster.f32 [%0], %1;" :: "r"(hps_peer + woff*4), "f"(hn) : "memory");
        if (t == TSTEPS-1) d_hT[(b0+ub)*128 + hk] = hn;
        asm volatile("barrier.cluster.arrive.aligned;" ::: "memory");
        asm volatile("barrier.cluster.wait.aligned;" ::: "memory");
    }
}

__global__ void k_fin(const float* __restrict__ fcW, const float* __restrict__ fcb,
                      float* __restrict__ out){
    __shared__ float r[128];
    int b = blockIdx.x, tid = threadIdx.x;
    float rep = d_gnum[b*128+tid] / (d_gden[b] + 1e-16f);
    float v = fcW[tid]*rep + fcW[128+tid]*d_hT[b*128+tid];
    r[tid] = v; __syncthreads();
    for (int off=64; off; off>>=1){
        if (tid < off) r[tid] += r[tid+off];
        __syncthreads();
    }
    if (tid == 0) out[b] = r[0] + fcb[0];
}

extern "C" void kernel_launch(void* const* d_in, const int* in_sizes, int n_in,
                              void* d_out, int out_size){
    const float* x      = (const float*)d_in[0];
    const int*   ei     = (const int*)  d_in[1];
    const int*   batch  = (const int*)  d_in[2];
    const float* quant  = (const float*)d_in[3];
    const float* gatW   = (const float*)d_in[4];
    const float* attS   = (const float*)d_in[5];
    const float* attD   = (const float*)d_in[6];
    const float* gatb   = (const float*)d_in[7];
    const float* g1     = (const float*)d_in[8];
    const float* b1     = (const float*)d_in[9];
    const float* m1     = (const float*)d_in[10];
    const float* v1     = (const float*)d_in[11];
    const float* gcnW   = (const float*)d_in[12];
    const float* gcnb   = (const float*)d_in[13];
    const float* g2     = (const float*)d_in[14];
    const float* b2     = (const float*)d_in[15];
    const float* m2     = (const float*)d_in[16];
    const float* v2     = (const float*)d_in[17];
    const float* gateW  = (const float*)d_in[18];
    const float* gateb  = (const float*)d_in[19];
    const float* Wih    = (const float*)d_in[20];
    const float* Whh    = (const float*)d_in[21];
    const float* bih    = (const float*)d_in[22];
    const float* bhh    = (const float*)d_in[23];
    const float* fcW    = (const float*)d_in[24];
    const float* fcb    = (const float*)d_in[25];
    float* out = (float*)d_out;

    cudaFuncSetAttribute(k_gemm, cudaFuncAttributeMaxDynamicSharedMemorySize, 73728);

    cudaStream_t sA, sB;
    cudaStreamCreateWithFlags(&sA, cudaStreamNonBlocking);
    cudaStreamCreateWithFlags(&sB, cudaStreamNonBlocking);
    cudaEvent_t eFork, eCsr, eLstm;
    cudaEventCreateWithFlags(&eFork, cudaEventDisableTiming);
    cudaEventCreateWithFlags(&eCsr,  cudaEventDisableTiming);
    cudaEventCreateWithFlags(&eLstm, cudaEventDisableTiming);

    cudaEventRecord(eFork, 0);
    cudaStreamWaitEvent(sA, eFork, 0);
    cudaStreamWaitEvent(sB, eFork, 0);

    // enqueue order chosen so launch #4 (ncu capture slot) = k_gemm (GEMM1)
    k_xp<<<256,512,0,sB>>>(quant, Wih, bih, bhh);          // 1
    k_init<<<196,256,0,sA>>>();                            // 2
    k_count<<<3125,256,0,sA>>>(ei);                        // 3
    k_gemm<<<444,128,73728>>>(x, gatW, attS, attD, 0);     // 4  <-- profiled
    k_scan1<<<196,256,0,sA>>>();                           // 5
    k_scan2<<<1,256,0,sA>>>();                             // 6
    k_scan3<<<196,256,0,sA>>>();                           // 7
    k_prep<<<196,256,0,sA>>>();                            // 8
    k_scatter<<<3125,256,0,sA>>>(ei);                      // 9
    cudaEventRecord(eCsr, sA);
    k_lstmp<<<128,256,0,sB>>>(Whh);                        // 10 (small smem: co-resides)
    cudaEventRecord(eLstm, sB);

    cudaStreamWaitEvent(0, eCsr, 0);
    k_gat<<<6250,256>>>(gatb, g1, b1, m1, v1);             // 11
    k_gemm<<<444,128,73728>>>(nullptr, gcnW, nullptr, nullptr, 1);  // 12
    k_gcn<<<6250,256>>>(batch, gcnb, g2, b2, m2, v2, gateW, gateb); // 13

    cudaStreamWaitEvent(0, eLstm, 0);
    k_fin<<<256,128>>>(fcW, fcb, out);                     // 14

    cudaStreamDestroy(sA);
    cudaStreamDestroy(sB);
    cudaEventDestroy(eFork);
    cudaEventDestroy(eCsr);
    cudaEventDestroy(eLstm);
    (void)in_sizes; (void)n_in; (void)out_size;
}

// round 10
// speedup vs baseline: 1.5261x; 1.0463x over previous
#include <cuda_runtime.h>

#define NN 50000
#define EE 800000
#define BBATCH 256
#define TSTEPS 50
#define FM 0xffffffffu

__device__ __align__(16) float d_xw[NN*128];
__device__ __align__(16) float d_h[NN*128];
__device__ __align__(16) float d_hw[NN*128];
__device__ __align__(16) float d_asrc[NN*4];
__device__ __align__(16) float d_adst[NN*4];
__device__ float d_dinv[NN];
__device__ int   d_deg[NN];
__device__ int   d_rowptr[NN+1];
__device__ int   d_cursor[NN];
__device__ int   d_colsrc[EE];
__device__ int   d_bsum[256], d_boff[256];
__device__ float d_gnum[BBATCH*128];
__device__ float d_gden[BBATCH];
__device__ __align__(16) float d_xp[BBATCH*TSTEPS*512];
__device__ float d_hT[BBATCH*128];

__device__ __forceinline__ float sigf(float x){ return __fdividef(1.f, 1.f + __expf(-x)); }
__device__ __forceinline__ float tanhfa(float x){ float e=__expf(2.f*x); return 1.f - __fdividef(2.f, e+1.f); }

__device__ __forceinline__ void ffma2(unsigned long long& d, unsigned long long a, unsigned long long b){
    asm("fma.rn.f32x2 %0, %1, %2, %0;" : "+l"(d) : "l"(a), "l"(b));
}
__device__ __forceinline__ float pairsum(unsigned long long v){
    float2 f; __builtin_memcpy(&f, &v, 8); return f.x + f.y;
}

__global__ void k_init(){
    int i = blockIdx.x*256 + threadIdx.x;
    if (i < NN) d_deg[i] = 0;
    if (i < BBATCH*128) d_gnum[i]=0.f;
    if (i < BBATCH) d_gden[i]=0.f;
}

__global__ void k_count(const int* __restrict__ ei){
    int i = blockIdx.x*256 + threadIdx.x;
    if (i < EE) atomicAdd(&d_deg[ei[EE+i]], 1);
}

__global__ void k_scan1(){
    __shared__ int s[256];
    int tid = threadIdx.x;
    int i = blockIdx.x*256 + tid;
    int v = (i < NN) ? d_deg[i] : 0;
    s[tid] = v; __syncthreads();
    for (int off=1; off<256; off<<=1){
        int t = (tid>=off) ? s[tid-off] : 0;
        __syncthreads(); s[tid] += t; __syncthreads();
    }
    if (i < NN) d_rowptr[i+1] = s[tid];
    if (tid == 255) d_bsum[blockIdx.x] = s[255];
}

__global__ void k_scan2(){
    __shared__ int s[256];
    int tid = threadIdx.x;
    int v = (tid < 196) ? d_bsum[tid] : 0;
    s[tid] = v; __syncthreads();
    for (int off=1; off<256; off<<=1){
        int t = (tid>=off) ? s[tid-off] : 0;
        __syncthreads(); s[tid] += t; __syncthreads();
    }
    if (tid < 196) d_boff[tid] = s[tid] - v;
}

__global__ void k_scan3(){
    int i = blockIdx.x*256 + threadIdx.x;
    if (i < NN) d_rowptr[i+1] += d_boff[blockIdx.x];
    if (i == 0) d_rowptr[0] = 0;
}

__global__ void k_prep(){
    int i = blockIdx.x*256 + threadIdx.x;
    if (i >= NN) return;
    int a = d_rowptr[i], b = d_rowptr[i+1];
    d_cursor[i] = a;
    d_dinv[i] = rsqrtf((float)(b - a + 1));
}

__global__ void k_scatter(const int* __restrict__ ei){
    int i = blockIdx.x*256 + threadIdx.x;
    if (i >= EE) return;
    int s = ei[i], d = ei[EE+i];
    int pos = atomicAdd(&d_cursor[d], 1);
    d_colsrc[pos] = s;
}

// GEMM v3: 256 threads, 64-row tile, 8 rows x 4 cols per thread, 2 blocks/SM.
// mode0: X=Xp, Y=d_xw + attention epilogue; mode1: X=d_h, Y=d_hw
__global__ void __launch_bounds__(256,2) k_gemm(const float* __restrict__ Xp,
                       const float* __restrict__ W,
                       const float* __restrict__ attS, const float* __restrict__ attD, int mode){
    extern __shared__ float sm[];
    float* Ws = sm;          // 128x128 = 16384 floats
    float* xs = sm + 16384;  // 64x128  =  8192 floats
    const float* X = mode ? d_h : Xp;
    float* Y = mode ? d_hw : d_xw;
    int tid = threadIdx.x, cg = tid & 31, rg = tid >> 5;
    for (int i = tid; i < 16384; i += 256) Ws[i] = W[i];
    float as0=0,as1=0,as2=0,as3=0, ad0=0,ad1=0,ad2=0,ad3=0;
    if (!mode){
        as0=attS[cg*4]; as1=attS[cg*4+1]; as2=attS[cg*4+2]; as3=attS[cg*4+3];
        ad0=attD[cg*4]; ad1=attD[cg*4+1]; ad2=attD[cg*4+2]; ad3=attD[cg*4+3];
    }
    __syncthreads();
    const float4* Ws4 = (const float4*)Ws;
    const int nchunk = (NN + 63) / 64;
    for (int chunk = blockIdx.x; chunk < nchunk; chunk += gridDim.x){
        int row0 = chunk*64;
        __syncthreads();
        for (int i = tid; i < 8192; i += 256){
            int r = i >> 7, k = i & 127;
            int gr = row0 + r;
            xs[i] = (gr < NN) ? X[gr*128 + k] : 0.f;
        }
        __syncthreads();
        float a[8][4];
        #pragma unroll
        for (int r=0;r<8;r++){ a[r][0]=0;a[r][1]=0;a[r][2]=0;a[r][3]=0; }
        const float* xb = xs + rg*8*128;
        #pragma unroll 4
        for (int k=0;k<128;k++){
            float4 wv = Ws4[k*32 + cg];
            #pragma unroll
            for (int r=0;r<8;r++){
                float xv = xb[r*128 + k];
                a[r][0]+=xv*wv.x; a[r][1]+=xv*wv.y; a[r][2]+=xv*wv.z; a[r][3]+=xv*wv.w;
            }
        }
        #pragma unroll
        for (int r=0;r<8;r++){
            int grow = row0 + rg*8 + r;
            if (grow < NN)
                *(float4*)&Y[grow*128 + cg*4] = make_float4(a[r][0],a[r][1],a[r][2],a[r][3]);
            if (!mode){
                float s = a[r][0]*as0 + a[r][1]*as1 + a[r][2]*as2 + a[r][3]*as3;
                float d = a[r][0]*ad0 + a[r][1]*ad1 + a[r][2]*ad2 + a[r][3]*ad3;
                #pragma unroll
                for (int off=4; off; off>>=1){
                    s += __shfl_xor_sync(FM, s, off);
                    d += __shfl_xor_sync(FM, d, off);
                }
                if ((cg & 7) == 0 && grow < NN){
                    d_asrc[grow*4 + (cg>>3)] = s;
                    d_adst[grow*4 + (cg>>3)] = d;
                }
            }
        }
    }
}

__global__ void k_gat(const float* __restrict__ gatb,
                      const float* __restrict__ g1, const float* __restrict__ b1,
                      const float* __restrict__ m1, const float* __restrict__ v1){
    __shared__ float sc[128], sh[128], gb[128];
    int tid = threadIdx.x;
    if (tid < 128){
        float s = g1[tid]*rsqrtf(v1[tid]+1e-5f);
        sc[tid]=s; sh[tid]=b1[tid]-m1[tid]*s; gb[tid]=gatb[tid];
    }
    __syncthreads();
    int lane = tid & 31;
    int node = blockIdx.x*8 + (tid>>5);
    if (node >= NN) return;
    int begin = d_rowptr[node], end = d_rowptr[node+1];
    float4 adv = *(const float4*)&d_adst[node*4];
    float n0=0,n1=0,n2=0,n3=0;
    float dn0=0,dn1=0,dn2=0,dn3=0;
    for (int base = begin; base < end; base += 32){
        int idx = base + lane;
        int sl = 0; float4 exl = make_float4(0,0,0,0);
        if (idx < end){
            sl = d_colsrc[idx];
            float4 as = *(const float4*)&d_asrc[sl*4];
            float e0 = as.x+adv.x; e0 = e0>0.f? e0 : 0.2f*e0;
            float e1 = as.y+adv.y; e1 = e1>0.f? e1 : 0.2f*e1;
            float e2 = as.z+adv.z; e2 = e2>0.f? e2 : 0.2f*e2;
            float e3 = as.w+adv.w; e3 = e3>0.f? e3 : 0.2f*e3;
            exl = make_float4(__expf(e0),__expf(e1),__expf(e2),__expf(e3));
            dn0+=exl.x; dn1+=exl.y; dn2+=exl.z; dn3+=exl.w;
        }
        int cnt = min(32, end-base);
        for (int j=0;j<cnt;j++){
            int sj = __shfl_sync(FM, sl, j);
            float a0=__shfl_sync(FM,exl.x,j), a1=__shfl_sync(FM,exl.y,j);
            float a2=__shfl_sync(FM,exl.z,j), a3=__shfl_sync(FM,exl.w,j);
            float aj = lane<8? a0 : lane<16? a1 : lane<24? a2 : a3;
            float4 xv = *(const float4*)&d_xw[sj*128 + lane*4];
            n0 += xv.x*aj; n1 += xv.y*aj; n2 += xv.z*aj; n3 += xv.w*aj;
        }
    }
    #pragma unroll
    for (int off=16; off; off>>=1){
        dn0 += __shfl_xor_sync(FM,dn0,off); dn1 += __shfl_xor_sync(FM,dn1,off);
        dn2 += __shfl_xor_sync(FM,dn2,off); dn3 += __shfl_xor_sync(FM,dn3,off);
    }
    float4 as = *(const float4*)&d_asrc[node*4];
    float e0=as.x+adv.x; e0=e0>0.f?e0:0.2f*e0; float x0=__expf(e0);
    float e1=as.y+adv.y; e1=e1>0.f?e1:0.2f*e1; float x1=__expf(e1);
    float e2=as.z+adv.z; e2=e2>0.f?e2:0.2f*e2; float x2=__expf(e2);
    float e3=as.w+adv.w; e3=e3>0.f?e3:0.2f*e3; float x3=__expf(e3);
    dn0+=x0; dn1+=x1; dn2+=x2; dn3+=x3;
    float4 xv = *(const float4*)&d_xw[node*128 + lane*4];
    float aself = lane<8? x0 : lane<16? x1 : lane<24? x2 : x3;
    n0 += xv.x*aself; n1 += xv.y*aself; n2 += xv.z*aself; n3 += xv.w*aself;
    float hd = lane<8? dn0 : lane<16? dn1 : lane<24? dn2 : dn3;
    float inv = 1.0f/(hd + 1e-16f);
    int col = lane*4;
    float o0 = n0*inv + gb[col];   o0 = o0>0.f? o0 : expm1f(o0); o0 = o0*sc[col]+sh[col];
    float o1 = n1*inv + gb[col+1]; o1 = o1>0.f? o1 : expm1f(o1); o1 = o1*sc[col+1]+sh[col+1];
    float o2 = n2*inv + gb[col+2]; o2 = o2>0.f? o2 : expm1f(o2); o2 = o2*sc[col+2]+sh[col+2];
    float o3 = n3*inv + gb[col+3]; o3 = o3>0.f? o3 : expm1f(o3); o3 = o3*sc[col+3]+sh[col+3];
    *(float4*)&d_h[node*128 + col] = make_float4(o0,o1,o2,o3);
}

__global__ void k_gcn(const int* __restrict__ batch,
                      const float* __restrict__ gcnb,
                      const float* __restrict__ g2, const float* __restrict__ b2,
                      const float* __restrict__ m2, const float* __restrict__ v2,
                      const float* __restrict__ gateW, const float* __restrict__ gateb){
    __shared__ float sc[128], sh[128], gb[128], gw[128];
    int tid = threadIdx.x;
    if (tid < 128){
        float s = g2[tid]*rsqrtf(v2[tid]+1e-5f);
        sc[tid]=s; sh[tid]=b2[tid]-m2[tid]*s; gb[tid]=gcnb[tid]; gw[tid]=gateW[tid];
    }
    __syncthreads();
    int lane = tid & 31;
    int node = blockIdx.x*8 + (tid>>5);
    if (node >= NN) return;
    int begin = d_rowptr[node], end = d_rowptr[node+1];
    float did = d_dinv[node];
    float a0=0,a1=0,a2=0,a3=0;
    for (int base = begin; base < end; base += 32){
        int idx = base + lane;
        int sl = 0; float dsl = 0.f;
        if (idx < end){ sl = d_colsrc[idx]; dsl = d_dinv[sl]; }
        int cnt = min(32, end-base);
        for (int j=0;j<cnt;j++){
            int sj = __shfl_sync(FM, sl, j);
            float ds = __shfl_sync(FM, dsl, j);
            float4 hv = *(const float4*)&d_hw[sj*128 + lane*4];
            a0 += hv.x*ds; a1 += hv.y*ds; a2 += hv.z*ds; a3 += hv.w*ds;
        }
    }
    int col = lane*4;
    float4 sv = *(const float4*)&d_hw[node*128 + col];
    float h0 = did*(a0 + did*sv.x) + gb[col];
    float h1 = did*(a1 + did*sv.y) + gb[col+1];
    float h2v = did*(a2 + did*sv.z) + gb[col+2];
    float h3 = did*(a3 + did*sv.w) + gb[col+3];
    h0 = h0>0.f? h0 : expm1f(h0); h0 = h0*sc[col]+sh[col];
    h1 = h1>0.f? h1 : expm1f(h1); h1 = h1*sc[col+1]+sh[col+1];
    h2v = h2v>0.f? h2v : expm1f(h2v); h2v = h2v*sc[col+2]+sh[col+2];
    h3 = h3>0.f? h3 : expm1f(h3); h3 = h3*sc[col+3]+sh[col+3];
    float g = h0*gw[col] + h1*gw[col+1] + h2v*gw[col+2] + h3*gw[col+3];
    #pragma unroll
    for (int off=16; off; off>>=1) g += __shfl_xor_sync(FM, g, off);
    g += gateb[0];
    float p = __expf(g);
    int b = batch[node];
    if (lane == 0) atomicAdd(&d_gden[b], p);
    atomicAdd(&d_gnum[b*128+col],   p*h0);
    atomicAdd(&d_gnum[b*128+col+1], p*h1);
    atomicAdd(&d_gnum[b*128+col+2], p*h2v);
    atomicAdd(&d_gnum[b*128+col+3], p*h3);
}

__global__ void k_xp(const float* __restrict__ quant, const float* __restrict__ Wih,
                     const float* __restrict__ bih, const float* __restrict__ bhh){
    __shared__ float qS[TSTEPS*32];
    int b = blockIdx.x, g = threadIdx.x;
    for (int i = g; i < TSTEPS*32; i += 512) qS[i] = quant[b*TSTEPS*32 + i];
    float4 wr[8];
    #pragma unroll
    for (int q=0;q<8;q++) wr[q] = *(const float4*)&Wih[g*32 + q*4];
    float bias = bih[g] + bhh[g];
    __syncthreads();
    const float4* qS4 = (const float4*)qS;
    for (int t=0; t<TSTEPS; t++){
        float acc = bias;
        #pragma unroll
        for (int q=0;q<8;q++){
            float4 xv = qS4[t*8+q];
            acc += wr[q].x*xv.x + wr[q].y*xv.y + wr[q].z*xv.z + wr[q].w*xv.w;
        }
        d_xp[(b*TSTEPS + t)*512 + g] = acc;
    }
}

// LSTM v3: weights in registers (64 x f32x2 per thread), h batch/k-pair transposed
// in 2KB smem, broadcast loads only. Cluster-2 splits the 128 units; DSMEM exchange.
__global__ void __cluster_dims__(2,1,1) __launch_bounds__(256,1)
k_lstmp(const float* __restrict__ Whh){
    __shared__ __align__(16) float hps[512];   // [k2][8]: b0k0,b0k1,b1k0,b1k1,b2k0,b2k1,b3k0,b3k1
    __shared__ float gbuf[1024];
    int tid = threadIdx.x;
    unsigned int rank;
    asm("mov.u32 %0, %%cluster_ctarank;" : "=r"(rank));
    int U0 = (int)rank * 64;
    int b0 = (blockIdx.x >> 1) * 4;
    int g = tid >> 6, ju = tid & 63;
    int row = g*128 + U0 + ju;

    union { unsigned long long u[64]; float4 v[32]; } W;
    {
        const float4* row4 = (const float4*)&Whh[row*128];
        #pragma unroll
        for (int j=0;j<32;j++) W.v[j] = row4[j];
    }
    for (int i = tid; i < 512; i += 256) hps[i] = 0.f;
    float creg = 0.f;
    __syncthreads();
    asm volatile("barrier.cluster.arrive.aligned;" ::: "memory");
    asm volatile("barrier.cluster.wait.aligned;" ::: "memory");

    unsigned int hps_addr;
    asm("{ .reg .u64 t; cvta.to.shared.u64 t, %1; cvt.u32.u64 %0, t; }" : "=r"(hps_addr) : "l"(hps));
    unsigned int peer = rank ^ 1u;
    unsigned int hps_peer;
    asm("mapa.shared::cluster.u32 %0, %1, %2;" : "=r"(hps_peer) : "r"(hps_addr), "r"(peer));

    const ulonglong2* hp4 = (const ulonglong2*)hps;
    int ub = tid >> 6, uju = tid & 63;
    int hk = U0 + uju;
    int woff = (hk>>1)*8 + (ub>>1)*4 + (ub&1)*2 + (hk&1);

    for (int t=0; t<TSTEPS; t++){
        float x0 = d_xp[((b0+0)*TSTEPS + t)*512 + row];
        float x1 = d_xp[((b0+1)*TSTEPS + t)*512 + row];
        float x2 = d_xp[((b0+2)*TSTEPS + t)*512 + row];
        float x3 = d_xp[((b0+3)*TSTEPS + t)*512 + row];
        unsigned long long a0=0,a1=0,a2=0,a3=0;
        #pragma unroll
        for (int k2=0;k2<64;k2++){
            ulonglong2 hA = hp4[2*k2];
            ulonglong2 hB = hp4[2*k2+1];
            ffma2(a0, W.u[k2], hA.x);
            ffma2(a1, W.u[k2], hA.y);
            ffma2(a2, W.u[k2], hB.x);
            ffma2(a3, W.u[k2], hB.y);
        }
        ((float4*)gbuf)[tid] = make_float4(pairsum(a0)+x0, pairsum(a1)+x1,
                                           pairsum(a2)+x2, pairsum(a3)+x3);
        __syncthreads();
        float gi = gbuf[(0*64+uju)*4 + ub];
        float gf = gbuf[(1*64+uju)*4 + ub];
        float gg = gbuf[(2*64+uju)*4 + ub];
        float go = gbuf[(3*64+uju)*4 + ub];
        float cn = sigf(gf)*creg + sigf(gi)*tanhfa(gg);
        creg = cn;
        float hn = sigf(go)*tanhfa(cn);
        hps[woff] = hn;
        asm volatile("st.shared::cluster.f32 [%0], %1;" :: "r"(hps_peer + woff*4), "f"(hn) : "memory");
        if (t == TSTEPS-1) d_hT[(b0+ub)*128 + hk] = hn;
        asm volatile("barrier.cluster.arrive.aligned;" ::: "memory");
        asm volatile("barrier.cluster.wait.aligned;" ::: "memory");
    }
}

__global__ void k_fin(const float* __restrict__ fcW, const float* __restrict__ fcb,
                      float* __restrict__ out){
    __shared__ float r[128];
    int b = blockIdx.x, tid = threadIdx.x;
    float rep = d_gnum[b*128+tid] / (d_gden[b] + 1e-16f);
    float v = fcW[tid]*rep + fcW[128+tid]*d_hT[b*128+tid];
    r[tid] = v; __syncthreads();
    for (int off=64; off; off>>=1){
        if (tid < off) r[tid] += r[tid+off];
        __syncthreads();
    }
    if (tid == 0) out[b] = r[0] + fcb[0];
}

extern "C" void kernel_launch(void* const* d_in, const int* in_sizes, int n_in,
                              void* d_out, int out_size){
    const float* x      = (const float*)d_in[0];
    const int*   ei     = (const int*)  d_in[1];
    const int*   batch  = (const int*)  d_in[2];
    const float* quant  = (const float*)d_in[3];
    const float* gatW   = (const float*)d_in[4];
    const float* attS   = (const float*)d_in[5];
    const float* attD   = (const float*)d_in[6];
    const float* gatb   = (const float*)d_in[7];
    const float* g1     = (const float*)d_in[8];
    const float* b1     = (const float*)d_in[9];
    const float* m1     = (const float*)d_in[10];
    const float* v1     = (const float*)d_in[11];
    const float* gcnW   = (const float*)d_in[12];
    const float* gcnb   = (const float*)d_in[13];
    const float* g2     = (const float*)d_in[14];
    const float* b2     = (const float*)d_in[15];
    const float* m2     = (const float*)d_in[16];
    const float* v2     = (const float*)d_in[17];
    const float* gateW  = (const float*)d_in[18];
    const float* gateb  = (const float*)d_in[19];
    const float* Wih    = (const float*)d_in[20];
    const float* Whh    = (const float*)d_in[21];
    const float* bih    = (const float*)d_in[22];
    const float* bhh    = (const float*)d_in[23];
    const float* fcW    = (const float*)d_in[24];
    const float* fcb    = (const float*)d_in[25];
    float* out = (float*)d_out;

    cudaFuncSetAttribute(k_gemm, cudaFuncAttributeMaxDynamicSharedMemorySize, 98304);

    cudaStream_t sA, sB;
    cudaStreamCreateWithFlags(&sA, cudaStreamNonBlocking);
    cudaStreamCreateWithFlags(&sB, cudaStreamNonBlocking);
    cudaEvent_t eFork, eCsr, eLstm;
    cudaEventCreateWithFlags(&eFork, cudaEventDisableTiming);
    cudaEventCreateWithFlags(&eCsr,  cudaEventDisableTiming);
    cudaEventCreateWithFlags(&eLstm, cudaEventDisableTiming);

    cudaEventRecord(eFork, 0);
    cudaStreamWaitEvent(sA, eFork, 0);
    cudaStreamWaitEvent(sB, eFork, 0);

    // enqueue order keeps launch #4 (ncu capture slot) = k_gemm (GEMM1)
    k_xp<<<256,512,0,sB>>>(quant, Wih, bih, bhh);          // 1
    k_init<<<196,256,0,sA>>>();                            // 2
    k_count<<<3125,256,0,sA>>>(ei);                        // 3
    k_gemm<<<296,256,98304>>>(x, gatW, attS, attD, 0);     // 4  <-- profiled
    k_scan1<<<196,256,0,sA>>>();                           // 5
    k_scan2<<<1,256,0,sA>>>();                             // 6
    k_scan3<<<196,256,0,sA>>>();                           // 7
    k_prep<<<196,256,0,sA>>>();                            // 8
    k_scatter<<<3125,256,0,sA>>>(ei);                      // 9
    cudaEventRecord(eCsr, sA);
    k_lstmp<<<128,256,0,sB>>>(Whh);                        // 10
    cudaEventRecord(eLstm, sB);

    cudaStreamWaitEvent(0, eCsr, 0);
    k_gat<<<6250,256>>>(gatb, g1, b1, m1, v1);             // 11
    k_gemm<<<296,256,98304>>>(nullptr, gcnW, nullptr, nullptr, 1);  // 12
    k_gcn<<<6250,256>>>(batch, gcnb, g2, b2, m2, v2, gateW, gateb); // 13

    cudaStreamWaitEvent(0, eLstm, 0);
    k_fin<<<256,128>>>(fcW, fcb, out);                     // 14

    cudaStreamDestroy(sA);
    cudaStreamDestroy(sB);
    cudaEventDestroy(eFork);
    cudaEventDestroy(eCsr);
    cudaEventDestroy(eLstm);
    (void)in_sizes; (void)n_in; (void)out_size;
}

// round 12
// speedup vs baseline: 1.5835x; 1.0376x over previous
#include <cuda_runtime.h>

#define NN 50000
#define EE 800000
#define BBATCH 256
#define TSTEPS 50
#define FM 0xffffffffu

__device__ __align__(16) float d_xw[NN*128];
__device__ __align__(16) float d_h[NN*128];
__device__ __align__(16) float d_hw[NN*128];
__device__ __align__(16) float d_asrc[NN*4];
__device__ __align__(16) float d_adst[NN*4];
__device__ float d_dinv[NN];
__device__ int   d_deg[NN];
__device__ int   d_rowptr[NN+1];
__device__ int   d_cursor[NN];
__device__ int   d_colsrc[EE];
__device__ int   d_bsum[256], d_boff[256];
__device__ float d_gnum[BBATCH*128];
__device__ float d_gden[BBATCH];
__device__ __align__(16) float d_xp[BBATCH*TSTEPS*512];
__device__ float d_hT[BBATCH*128];

__device__ __forceinline__ float sigf(float x){ return __fdividef(1.f, 1.f + __expf(-x)); }
__device__ __forceinline__ float tanhfa(float x){ float e=__expf(2.f*x); return 1.f - __fdividef(2.f, e+1.f); }

__device__ __forceinline__ void ffma2(unsigned long long& d, unsigned long long a, unsigned long long b){
    asm("fma.rn.f32x2 %0, %1, %2, %0;" : "+l"(d) : "l"(a), "l"(b));
}
__device__ __forceinline__ unsigned long long dup2(float x){
    unsigned long long r;
    asm("mov.b64 %0, {%1, %1};" : "=l"(r) : "f"(x));
    return r;
}
__device__ __forceinline__ float pairsum(unsigned long long v){
    float2 f; __builtin_memcpy(&f, &v, 8); return f.x + f.y;
}
__device__ __forceinline__ float2 unpack2(unsigned long long v){
    float2 f; __builtin_memcpy(&f, &v, 8); return f;
}

__global__ void k_init(){
    int i = blockIdx.x*256 + threadIdx.x;
    if (i < NN) d_deg[i] = 0;
    if (i < BBATCH*128) d_gnum[i]=0.f;
    if (i < BBATCH) d_gden[i]=0.f;
}

__global__ void k_count(const int* __restrict__ ei){
    int i = blockIdx.x*256 + threadIdx.x;
    if (i < EE) atomicAdd(&d_deg[ei[EE+i]], 1);
}

__global__ void k_scan1(){
    __shared__ int s[256];
    int tid = threadIdx.x;
    int i = blockIdx.x*256 + tid;
    int v = (i < NN) ? d_deg[i] : 0;
    s[tid] = v; __syncthreads();
    for (int off=1; off<256; off<<=1){
        int t = (tid>=off) ? s[tid-off] : 0;
        __syncthreads(); s[tid] += t; __syncthreads();
    }
    if (i < NN) d_rowptr[i+1] = s[tid];
    if (tid == 255) d_bsum[blockIdx.x] = s[255];
}

__global__ void k_scan2(){
    __shared__ int s[256];
    int tid = threadIdx.x;
    int v = (tid < 196) ? d_bsum[tid] : 0;
    s[tid] = v; __syncthreads();
    for (int off=1; off<256; off<<=1){
        int t = (tid>=off) ? s[tid-off] : 0;
        __syncthreads(); s[tid] += t; __syncthreads();
    }
    if (tid < 196) d_boff[tid] = s[tid] - v;
}

__global__ void k_scan3(){
    int i = blockIdx.x*256 + threadIdx.x;
    if (i < NN) d_rowptr[i+1] += d_boff[blockIdx.x];
    if (i == 0) d_rowptr[0] = 0;
}

__global__ void k_prep(){
    int i = blockIdx.x*256 + threadIdx.x;
    if (i >= NN) return;
    int a = d_rowptr[i], b = d_rowptr[i+1];
    d_cursor[i] = a;
    d_dinv[i] = rsqrtf((float)(b - a + 1));
}

__global__ void k_scatter(const int* __restrict__ ei){
    int i = blockIdx.x*256 + threadIdx.x;
    if (i >= EE) return;
    int s = ei[i], d = ei[EE+i];
    int pos = atomicAdd(&d_cursor[d], 1);
    d_colsrc[pos] = s;
}

// GEMM v4: 256 threads, 64-row tile, 8 rows x 4 cols per thread, 2 blocks/SM,
// packed f32x2 FFMA: W col-pairs native in row-major float4; x via LDS.64 k-pairs + dup.
__global__ void __launch_bounds__(256,2) k_gemm(const float* __restrict__ Xp,
                       const float* __restrict__ W,
                       const float* __restrict__ attS, const float* __restrict__ attD, int mode){
    extern __shared__ float sm[];
    float* Ws = sm;          // 128x128 = 16384 floats
    float* xs = sm + 16384;  // 64x128  =  8192 floats
    const float* X = mode ? d_h : Xp;
    float* Y = mode ? d_hw : d_xw;
    int tid = threadIdx.x, cg = tid & 31, rg = tid >> 5;
    for (int i = tid; i < 16384; i += 256) Ws[i] = W[i];
    float as0=0,as1=0,as2=0,as3=0, ad0=0,ad1=0,ad2=0,ad3=0;
    if (!mode){
        as0=attS[cg*4]; as1=attS[cg*4+1]; as2=attS[cg*4+2]; as3=attS[cg*4+3];
        ad0=attD[cg*4]; ad1=attD[cg*4+1]; ad2=attD[cg*4+2]; ad3=attD[cg*4+3];
    }
    __syncthreads();
    const ulonglong2* Wsp = (const ulonglong2*)Ws;   // [k*32+cg] -> {(w0,w1),(w2,w3)}
    const int nchunk = (NN + 63) / 64;
    for (int chunk = blockIdx.x; chunk < nchunk; chunk += gridDim.x){
        int row0 = chunk*64;
        __syncthreads();
        for (int i = tid; i < 8192; i += 256){
            int r = i >> 7, k = i & 127;
            int gr = row0 + r;
            xs[i] = (gr < NN) ? X[gr*128 + k] : 0.f;
        }
        __syncthreads();
        unsigned long long acc[8][2];
        #pragma unroll
        for (int r=0;r<8;r++){ acc[r][0]=0ull; acc[r][1]=0ull; }
        const float* xb = xs + rg*8*128;
        #pragma unroll 4
        for (int k2=0;k2<64;k2++){
            int k = k2*2;
            ulonglong2 w0 = Wsp[k*32 + cg];
            ulonglong2 w1 = Wsp[(k+1)*32 + cg];
            #pragma unroll
            for (int r=0;r<8;r++){
                float2 xv = *(const float2*)&xb[r*128 + k];
                unsigned long long xa = dup2(xv.x);
                unsigned long long xc = dup2(xv.y);
                ffma2(acc[r][0], xa, w0.x); ffma2(acc[r][1], xa, w0.y);
                ffma2(acc[r][0], xc, w1.x); ffma2(acc[r][1], xc, w1.y);
            }
        }
        #pragma unroll
        for (int r=0;r<8;r++){
            int grow = row0 + rg*8 + r;
            float2 p01 = unpack2(acc[r][0]);
            float2 p23 = unpack2(acc[r][1]);
            if (grow < NN)
                *(float4*)&Y[grow*128 + cg*4] = make_float4(p01.x,p01.y,p23.x,p23.y);
            if (!mode){
                float s = p01.x*as0 + p01.y*as1 + p23.x*as2 + p23.y*as3;
                float d = p01.x*ad0 + p01.y*ad1 + p23.x*ad2 + p23.y*ad3;
                #pragma unroll
                for (int off=4; off; off>>=1){
                    s += __shfl_xor_sync(FM, s, off);
                    d += __shfl_xor_sync(FM, d, off);
                }
                if ((cg & 7) == 0 && grow < NN){
                    d_asrc[grow*4 + (cg>>3)] = s;
                    d_adst[grow*4 + (cg>>3)] = d;
                }
            }
        }
    }
}

__global__ void k_gat(const float* __restrict__ gatb,
                      const float* __restrict__ g1, const float* __restrict__ b1,
                      const float* __restrict__ m1, const float* __restrict__ v1){
    __shared__ float sc[128], sh[128], gb[128];
    int tid = threadIdx.x;
    if (tid < 128){
        float s = g1[tid]*rsqrtf(v1[tid]+1e-5f);
        sc[tid]=s; sh[tid]=b1[tid]-m1[tid]*s; gb[tid]=gatb[tid];
    }
    __syncthreads();
    int lane = tid & 31;
    int node = blockIdx.x*8 + (tid>>5);
    if (node >= NN) return;
    int begin = d_rowptr[node], end = d_rowptr[node+1];
    float4 adv = *(const float4*)&d_adst[node*4];
    float n0=0,n1=0,n2=0,n3=0;
    float dn0=0,dn1=0,dn2=0,dn3=0;
    for (int base = begin; base < end; base += 32){
        int idx = base + lane;
        int sl = 0; float4 exl = make_float4(0,0,0,0);
        if (idx < end){
            sl = d_colsrc[idx];
            float4 as = *(const float4*)&d_asrc[sl*4];
            float e0 = as.x+adv.x; e0 = e0>0.f? e0 : 0.2f*e0;
            float e1 = as.y+adv.y; e1 = e1>0.f? e1 : 0.2f*e1;
            float e2 = as.z+adv.z; e2 = e2>0.f? e2 : 0.2f*e2;
            float e3 = as.w+adv.w; e3 = e3>0.f? e3 : 0.2f*e3;
            exl = make_float4(__expf(e0),__expf(e1),__expf(e2),__expf(e3));
            dn0+=exl.x; dn1+=exl.y; dn2+=exl.z; dn3+=exl.w;
        }
        int cnt = min(32, end-base);
        for (int j=0;j<cnt;j++){
            int sj = __shfl_sync(FM, sl, j);
            float a0=__shfl_sync(FM,exl.x,j), a1=__shfl_sync(FM,exl.y,j);
            float a2=__shfl_sync(FM,exl.z,j), a3=__shfl_sync(FM,exl.w,j);
            float aj = lane<8? a0 : lane<16? a1 : lane<24? a2 : a3;
            float4 xv = *(const float4*)&d_xw[sj*128 + lane*4];
            n0 += xv.x*aj; n1 += xv.y*aj; n2 += xv.z*aj; n3 += xv.w*aj;
        }
    }
    #pragma unroll
    for (int off=16; off; off>>=1){
        dn0 += __shfl_xor_sync(FM,dn0,off); dn1 += __shfl_xor_sync(FM,dn1,off);
        dn2 += __shfl_xor_sync(FM,dn2,off); dn3 += __shfl_xor_sync(FM,dn3,off);
    }
    float4 as = *(const float4*)&d_asrc[node*4];
    float e0=as.x+adv.x; e0=e0>0.f?e0:0.2f*e0; float x0=__expf(e0);
    float e1=as.y+adv.y; e1=e1>0.f?e1:0.2f*e1; float x1=__expf(e1);
    float e2=as.z+adv.z; e2=e2>0.f?e2:0.2f*e2; float x2=__expf(e2);
    float e3=as.w+adv.w; e3=e3>0.f?e3:0.2f*e3; float x3=__expf(e3);
    dn0+=x0; dn1+=x1; dn2+=x2; dn3+=x3;
    float4 xv = *(const float4*)&d_xw[node*128 + lane*4];
    float aself = lane<8? x0 : lane<16? x1 : lane<24? x2 : x3;
    n0 += xv.x*aself; n1 += xv.y*aself; n2 += xv.z*aself; n3 += xv.w*aself;
    float hd = lane<8? dn0 : lane<16? dn1 : lane<24? dn2 : dn3;
    float inv = 1.0f/(hd + 1e-16f);
    int col = lane*4;
    float o0 = n0*inv + gb[col];   o0 = o0>0.f? o0 : expm1f(o0); o0 = o0*sc[col]+sh[col];
    float o1 = n1*inv + gb[col+1]; o1 = o1>0.f? o1 : expm1f(o1); o1 = o1*sc[col+1]+sh[col+1];
    float o2 = n2*inv + gb[col+2]; o2 = o2>0.f? o2 : expm1f(o2); o2 = o2*sc[col+2]+sh[col+2];
    float o3 = n3*inv + gb[col+3]; o3 = o3>0.f? o3 : expm1f(o3); o3 = o3*sc[col+3]+sh[col+3];
    *(float4*)&d_h[node*128 + col] = make_float4(o0,o1,o2,o3);
}

__global__ void k_gcn(const int* __restrict__ batch,
                      const float* __restrict__ gcnb,
                      const float* __restrict__ g2, const float* __restrict__ b2,
                      const float* __restrict__ m2, const float* __restrict__ v2,
                      const float* __restrict__ gateW, const float* __restrict__ gateb){
    __shared__ float sc[128], sh[128], gb[128], gw[128];
    int tid = threadIdx.x;
    if (tid < 128){
        float s = g2[tid]*rsqrtf(v2[tid]+1e-5f);
        sc[tid]=s; sh[tid]=b2[tid]-m2[tid]*s; gb[tid]=gcnb[tid]; gw[tid]=gateW[tid];
    }
    __syncthreads();
    int lane = tid & 31;
    int node = blockIdx.x*8 + (tid>>5);
    if (node >= NN) return;
    int begin = d_rowptr[node], end = d_rowptr[node+1];
    float did = d_dinv[node];
    float a0=0,a1=0,a2=0,a3=0;
    for (int base = begin; base < end; base += 32){
        int idx = base + lane;
        int sl = 0; float dsl = 0.f;
        if (idx < end){ sl = d_colsrc[idx]; dsl = d_dinv[sl]; }
        int cnt = min(32, end-base);
        for (int j=0;j<cnt;j++){
            int sj = __shfl_sync(FM, sl, j);
            float ds = __shfl_sync(FM, dsl, j);
            float4 hv = *(const float4*)&d_hw[sj*128 + lane*4];
            a0 += hv.x*ds; a1 += hv.y*ds; a2 += hv.z*ds; a3 += hv.w*ds;
        }
    }
    int col = lane*4;
    float4 sv = *(const float4*)&d_hw[node*128 + col];
    float h0 = did*(a0 + did*sv.x) + gb[col];
    float h1 = did*(a1 + did*sv.y) + gb[col+1];
    float h2v = did*(a2 + did*sv.z) + gb[col+2];
    float h3 = did*(a3 + did*sv.w) + gb[col+3];
    h0 = h0>0.f? h0 : expm1f(h0); h0 = h0*sc[col]+sh[col];
    h1 = h1>0.f? h1 : expm1f(h1); h1 = h1*sc[col+1]+sh[col+1];
    h2v = h2v>0.f? h2v : expm1f(h2v); h2v = h2v*sc[col+2]+sh[col+2];
    h3 = h3>0.f? h3 : expm1f(h3); h3 = h3*sc[col+3]+sh[col+3];
    float g = h0*gw[col] + h1*gw[col+1] + h2v*gw[col+2] + h3*gw[col+3];
    #pragma unroll
    for (int off=16; off; off>>=1) g += __shfl_xor_sync(FM, g, off);
    g += gateb[0];
    float p = __expf(g);
    int b = batch[node];
    if (lane == 0) atomicAdd(&d_gden[b], p);
    atomicAdd(&d_gnum[b*128+col],   p*h0);
    atomicAdd(&d_gnum[b*128+col+1], p*h1);
    atomicAdd(&d_gnum[b*128+col+2], p*h2v);
    atomicAdd(&d_gnum[b*128+col+3], p*h3);
}

__global__ void k_xp(const float* __restrict__ quant, const float* __restrict__ Wih,
                     const float* __restrict__ bih, const float* __restrict__ bhh){
    __shared__ float qS[TSTEPS*32];
    int b = blockIdx.x, g = threadIdx.x;
    for (int i = g; i < TSTEPS*32; i += 512) qS[i] = quant[b*TSTEPS*32 + i];
    float4 wr[8];
    #pragma unroll
    for (int q=0;q<8;q++) wr[q] = *(const float4*)&Wih[g*32 + q*4];
    float bias = bih[g] + bhh[g];
    __syncthreads();
    const float4* qS4 = (const float4*)qS;
    for (int t=0; t<TSTEPS; t++){
        float acc = bias;
        #pragma unroll
        for (int q=0;q<8;q++){
            float4 xv = qS4[t*8+q];
            acc += wr[q].x*xv.x + wr[q].y*xv.y + wr[q].z*xv.z + wr[q].w*xv.w;
        }
        d_xp[(b*TSTEPS + t)*512 + g] = acc;
    }
}

// LSTM v3: weights in registers (64 x f32x2 per thread), h batch/k-pair transposed
// in 2KB smem, broadcast loads only. Cluster-2 splits the 128 units; DSMEM exchange.
__global__ void __cluster_dims__(2,1,1) __launch_bounds__(256,1)
k_lstmp(const float* __restrict__ Whh){
    __shared__ __align__(16) float hps[512];
    __shared__ float gbuf[1024];
    int tid = threadIdx.x;
    unsigned int rank;
    asm("mov.u32 %0, %%cluster_ctarank;" : "=r"(rank));
    int U0 = (int)rank * 64;
    int b0 = (blockIdx.x >> 1) * 4;
    int g = tid >> 6, ju = tid & 63;
    int row = g*128 + U0 + ju;

    union { unsigned long long u[64]; float4 v[32]; } W;
    {
        const float4* row4 = (const float4*)&Whh[row*128];
        #pragma unroll
        for (int j=0;j<32;j++) W.v[j] = row4[j];
    }
    for (int i = tid; i < 512; i += 256) hps[i] = 0.f;
    float creg = 0.f;
    __syncthreads();
    asm volatile("barrier.cluster.arrive.aligned;" ::: "memory");
    asm volatile("barrier.cluster.wait.aligned;" ::: "memory");

    unsigned int hps_addr;
    asm("{ .reg .u64 t; cvta.to.shared.u64 t, %1; cvt.u32.u64 %0, t; }" : "=r"(hps_addr) : "l"(hps));
    unsigned int peer = rank ^ 1u;
    unsigned int hps_peer;
    asm("mapa.shared::cluster.u32 %0, %1, %2;" : "=r"(hps_peer) : "r"(hps_addr), "r"(peer));

    const ulonglong2* hp4 = (const ulonglong2*)hps;
    int ub = tid >> 6, uju = tid & 63;
    int hk = U0 + uju;
    int woff = (hk>>1)*8 + (ub>>1)*4 + (ub&1)*2 + (hk&1);

    for (int t=0; t<TSTEPS; t++){
        float x0 = d_xp[((b0+0)*TSTEPS + t)*512 + row];
        float x1 = d_xp[((b0+1)*TSTEPS + t)*512 + row];
        float x2 = d_xp[((b0+2)*TSTEPS + t)*512 + row];
        float x3 = d_xp[((b0+3)*TSTEPS + t)*512 + row];
        unsigned long long a0=0,a1=0,a2=0,a3=0;
        #pragma unroll
        for (int k2=0;k2<64;k2++){
            ulonglong2 hA = hp4[2*k2];
            ulonglong2 hB = hp4[2*k2+1];
            ffma2(a0, W.u[k2], hA.x);
            ffma2(a1, W.u[k2], hA.y);
            ffma2(a2, W.u[k2], hB.x);
            ffma2(a3, W.u[k2], hB.y);
        }
        ((float4*)gbuf)[tid] = make_float4(pairsum(a0)+x0, pairsum(a1)+x1,
                                           pairsum(a2)+x2, pairsum(a3)+x3);
        __syncthreads();
        float gi = gbuf[(0*64+uju)*4 + ub];
        float gf = gbuf[(1*64+uju)*4 + ub];
        float gg = gbuf[(2*64+uju)*4 + ub];
        float go = gbuf[(3*64+uju)*4 + ub];
        float cn = sigf(gf)*creg + sigf(gi)*tanhfa(gg);
        creg = cn;
        float hn = sigf(go)*tanhfa(cn);
        hps[woff] = hn;
        asm volatile("st.shared::cluster.f32 [%0], %1;" :: "r"(hps_peer + woff*4), "f"(hn) : "memory");
        if (t == TSTEPS-1) d_hT[(b0+ub)*128 + hk] = hn;
        asm volatile("barrier.cluster.arrive.aligned;" ::: "memory");
        asm volatile("barrier.cluster.wait.aligned;" ::: "memory");
    }
}

__global__ void k_fin(const float* __restrict__ fcW, const float* __restrict__ fcb,
                      float* __restrict__ out){
    __shared__ float r[128];
    int b = blockIdx.x, tid = threadIdx.x;
    float rep = d_gnum[b*128+tid] / (d_gden[b] + 1e-16f);
    float v = fcW[tid]*rep + fcW[128+tid]*d_hT[b*128+tid];
    r[tid] = v; __syncthreads();
    for (int off=64; off; off>>=1){
        if (tid < off) r[tid] += r[tid+off];
        __syncthreads();
    }
    if (tid == 0) out[b] = r[0] + fcb[0];
}

extern "C" void kernel_launch(void* const* d_in, const int* in_sizes, int n_in,
                              void* d_out, int out_size){
    const float* x      = (const float*)d_in[0];
    const int*   ei     = (const int*)  d_in[1];
    const int*   batch  = (const int*)  d_in[2];
    const float* quant  = (const float*)d_in[3];
    const float* gatW   = (const float*)d_in[4];
    const float* attS   = (const float*)d_in[5];
    const float* attD   = (const float*)d_in[6];
    const float* gatb   = (const float*)d_in[7];
    const float* g1     = (const float*)d_in[8];
    const float* b1     = (const float*)d_in[9];
    const float* m1     = (const float*)d_in[10];
    const float* v1     = (const float*)d_in[11];
    const float* gcnW   = (const float*)d_in[12];
    const float* gcnb   = (const float*)d_in[13];
    const float* g2     = (const float*)d_in[14];
    const float* b2     = (const float*)d_in[15];
    const float* m2     = (const float*)d_in[16];
    const float* v2     = (const float*)d_in[17];
    const float* gateW  = (const float*)d_in[18];
    const float* gateb  = (const float*)d_in[19];
    const float* Wih    = (const float*)d_in[20];
    const float* Whh    = (const float*)d_in[21];
    const float* bih    = (const float*)d_in[22];
    const float* bhh    = (const float*)d_in[23];
    const float* fcW    = (const float*)d_in[24];
    const float* fcb    = (const float*)d_in[25];
    float* out = (float*)d_out;

    cudaFuncSetAttribute(k_gemm, cudaFuncAttributeMaxDynamicSharedMemorySize, 98304);

    cudaStream_t sA, sB;
    cudaStreamCreateWithFlags(&sA, cudaStreamNonBlocking);
    cudaStreamCreateWithFlags(&sB, cudaStreamNonBlocking);
    cudaEvent_t eFork, eCsr, eLstm;
    cudaEventCreateWithFlags(&eFork, cudaEventDisableTiming);
    cudaEventCreateWithFlags(&eCsr,  cudaEventDisableTiming);
    cudaEventCreateWithFlags(&eLstm, cudaEventDisableTiming);

    cudaEventRecord(eFork, 0);
    cudaStreamWaitEvent(sA, eFork, 0);
    cudaStreamWaitEvent(sB, eFork, 0);

    // enqueue order keeps launch #4 (ncu capture slot) = k_gemm (GEMM1)
    k_xp<<<256,512,0,sB>>>(quant, Wih, bih, bhh);          // 1
    k_init<<<196,256,0,sA>>>();                            // 2
    k_count<<<3125,256,0,sA>>>(ei);                        // 3
    k_gemm<<<296,256,98304>>>(x, gatW, attS, attD, 0);     // 4  <-- profiled
    k_scan1<<<196,256,0,sA>>>();                           // 5
    k_scan2<<<1,256,0,sA>>>();                             // 6
    k_scan3<<<196,256,0,sA>>>();                           // 7
    k_prep<<<196,256,0,sA>>>();                            // 8
    k_scatter<<<3125,256,0,sA>>>(ei);                      // 9
    cudaEventRecord(eCsr, sA);
    k_lstmp<<<128,256,0,sB>>>(Whh);                        // 10
    cudaEventRecord(eLstm, sB);

    cudaStreamWaitEvent(0, eCsr, 0);
    k_gat<<<6250,256>>>(gatb, g1, b1, m1, v1);             // 11
    k_gemm<<<296,256,98304>>>(nullptr, gcnW, nullptr, nullptr, 1);  // 12
    k_gcn<<<6250,256>>>(batch, gcnb, g2, b2, m2, v2, gateW, gateb); // 13

    cudaStreamWaitEvent(0, eLstm, 0);
    k_fin<<<256,128>>>(fcW, fcb, out);                     // 14

    cudaStreamDestroy(sA);
    cudaStreamDestroy(sB);
    cudaEventDestroy(eFork);
    cudaEventDestroy(eCsr);
    cudaEventDestroy(eLstm);
    (void)in_sizes; (void)n_in; (void)out_size;
}

// round 13
// speedup vs baseline: 1.6197x; 1.0229x over previous
#include <cuda_runtime.h>

#define NN 50000
#define EE 800000
#define BBATCH 256
#define TSTEPS 50
#define FM 0xffffffffu

__device__ __align__(16) float d_xw[NN*128];
__device__ __align__(16) float d_h[NN*128];
__device__ __align__(16) float d_hw[NN*128];
__device__ __align__(16) float d_asrc[NN*4];
__device__ __align__(16) float d_adst[NN*4];
__device__ float d_dinv[NN];
__device__ int   d_deg[NN];
__device__ int   d_rowptr[NN+1];
__device__ int   d_cursor[NN];
__device__ int   d_colsrc[EE];
__device__ int   d_bsum[256], d_boff[256];
__device__ float d_gnum[BBATCH*128];
__device__ float d_gden[BBATCH];
__device__ __align__(16) float d_xp[BBATCH*TSTEPS*512];
__device__ float d_hT[BBATCH*128];

__device__ __forceinline__ float sigf(float x){ return __fdividef(1.f, 1.f + __expf(-x)); }
__device__ __forceinline__ float tanhfa(float x){ float e=__expf(2.f*x); return 1.f - __fdividef(2.f, e+1.f); }

__device__ __forceinline__ void ffma2(unsigned long long& d, unsigned long long a, unsigned long long b){
    asm("fma.rn.f32x2 %0, %1, %2, %0;" : "+l"(d) : "l"(a), "l"(b));
}
__device__ __forceinline__ unsigned long long dup2(float x){
    unsigned long long r;
    asm("mov.b64 %0, {%1, %1};" : "=l"(r) : "f"(x));
    return r;
}
__device__ __forceinline__ float pairsum(unsigned long long v){
    float2 f; __builtin_memcpy(&f, &v, 8); return f.x + f.y;
}
__device__ __forceinline__ float2 unpack2(unsigned long long v){
    float2 f; __builtin_memcpy(&f, &v, 8); return f;
}

__global__ void k_init(){
    int i = blockIdx.x*256 + threadIdx.x;
    if (i < NN) d_deg[i] = 0;
    if (i < BBATCH*128) d_gnum[i]=0.f;
    if (i < BBATCH) d_gden[i]=0.f;
}

__global__ void k_count(const int* __restrict__ ei){
    int i = blockIdx.x*256 + threadIdx.x;
    if (i < EE) atomicAdd(&d_deg[ei[EE+i]], 1);
}

__global__ void k_scan1(){
    __shared__ int s[256];
    int tid = threadIdx.x;
    int i = blockIdx.x*256 + tid;
    int v = (i < NN) ? d_deg[i] : 0;
    s[tid] = v; __syncthreads();
    for (int off=1; off<256; off<<=1){
        int t = (tid>=off) ? s[tid-off] : 0;
        __syncthreads(); s[tid] += t; __syncthreads();
    }
    if (i < NN) d_rowptr[i+1] = s[tid];
    if (tid == 255) d_bsum[blockIdx.x] = s[255];
}

__global__ void k_scan2(){
    __shared__ int s[256];
    int tid = threadIdx.x;
    int v = (tid < 196) ? d_bsum[tid] : 0;
    s[tid] = v; __syncthreads();
    for (int off=1; off<256; off<<=1){
        int t = (tid>=off) ? s[tid-off] : 0;
        __syncthreads(); s[tid] += t; __syncthreads();
    }
    if (tid < 196) d_boff[tid] = s[tid] - v;
}

__global__ void k_scan3(){
    int i = blockIdx.x*256 + threadIdx.x;
    if (i < NN) d_rowptr[i+1] += d_boff[blockIdx.x];
    if (i == 0) d_rowptr[0] = 0;
}

__global__ void k_prep(){
    int i = blockIdx.x*256 + threadIdx.x;
    if (i >= NN) return;
    int a = d_rowptr[i], b = d_rowptr[i+1];
    d_cursor[i] = a;
    d_dinv[i] = rsqrtf((float)(b - a + 1));
}

__global__ void k_scatter(const int* __restrict__ ei){
    int i = blockIdx.x*256 + threadIdx.x;
    if (i >= EE) return;
    int s = ei[i], d = ei[EE+i];
    int pos = atomicAdd(&d_cursor[d], 1);
    d_colsrc[pos] = s;
}

// GEMM v4 (unchanged from R12)
__global__ void __launch_bounds__(256,2) k_gemm(const float* __restrict__ Xp,
                       const float* __restrict__ W,
                       const float* __restrict__ attS, const float* __restrict__ attD, int mode){
    extern __shared__ float sm[];
    float* Ws = sm;
    float* xs = sm + 16384;
    const float* X = mode ? d_h : Xp;
    float* Y = mode ? d_hw : d_xw;
    int tid = threadIdx.x, cg = tid & 31, rg = tid >> 5;
    for (int i = tid; i < 16384; i += 256) Ws[i] = W[i];
    float as0=0,as1=0,as2=0,as3=0, ad0=0,ad1=0,ad2=0,ad3=0;
    if (!mode){
        as0=attS[cg*4]; as1=attS[cg*4+1]; as2=attS[cg*4+2]; as3=attS[cg*4+3];
        ad0=attD[cg*4]; ad1=attD[cg*4+1]; ad2=attD[cg*4+2]; ad3=attD[cg*4+3];
    }
    __syncthreads();
    const ulonglong2* Wsp = (const ulonglong2*)Ws;
    const int nchunk = (NN + 63) / 64;
    for (int chunk = blockIdx.x; chunk < nchunk; chunk += gridDim.x){
        int row0 = chunk*64;
        __syncthreads();
        for (int i = tid; i < 8192; i += 256){
            int r = i >> 7, k = i & 127;
            int gr = row0 + r;
            xs[i] = (gr < NN) ? X[gr*128 + k] : 0.f;
        }
        __syncthreads();
        unsigned long long acc[8][2];
        #pragma unroll
        for (int r=0;r<8;r++){ acc[r][0]=0ull; acc[r][1]=0ull; }
        const float* xb = xs + rg*8*128;
        #pragma unroll 4
        for (int k2=0;k2<64;k2++){
            int k = k2*2;
            ulonglong2 w0 = Wsp[k*32 + cg];
            ulonglong2 w1 = Wsp[(k+1)*32 + cg];
            #pragma unroll
            for (int r=0;r<8;r++){
                float2 xv = *(const float2*)&xb[r*128 + k];
                unsigned long long xa = dup2(xv.x);
                unsigned long long xc = dup2(xv.y);
                ffma2(acc[r][0], xa, w0.x); ffma2(acc[r][1], xa, w0.y);
                ffma2(acc[r][0], xc, w1.x); ffma2(acc[r][1], xc, w1.y);
            }
        }
        #pragma unroll
        for (int r=0;r<8;r++){
            int grow = row0 + rg*8 + r;
            float2 p01 = unpack2(acc[r][0]);
            float2 p23 = unpack2(acc[r][1]);
            if (grow < NN)
                *(float4*)&Y[grow*128 + cg*4] = make_float4(p01.x,p01.y,p23.x,p23.y);
            if (!mode){
                float s = p01.x*as0 + p01.y*as1 + p23.x*as2 + p23.y*as3;
                float d = p01.x*ad0 + p01.y*ad1 + p23.x*ad2 + p23.y*ad3;
                #pragma unroll
                for (int off=4; off; off>>=1){
                    s += __shfl_xor_sync(FM, s, off);
                    d += __shfl_xor_sync(FM, d, off);
                }
                if ((cg & 7) == 0 && grow < NN){
                    d_asrc[grow*4 + (cg>>3)] = s;
                    d_adst[grow*4 + (cg>>3)] = d;
                }
            }
        }
    }
}

// GAT aggregation v2: smem-staged edge metadata, prefetched row gather, packed ffma2.
__global__ void k_gat(const float* __restrict__ gatb,
                      const float* __restrict__ g1, const float* __restrict__ b1,
                      const float* __restrict__ m1, const float* __restrict__ v1){
    __shared__ float sc[128], sh[128], gb[128];
    __shared__ int   sjs[8][32];
    __shared__ __align__(16) float sex[8][32][4];
    int tid = threadIdx.x;
    if (tid < 128){
        float s = g1[tid]*rsqrtf(v1[tid]+1e-5f);
        sc[tid]=s; sh[tid]=b1[tid]-m1[tid]*s; gb[tid]=gatb[tid];
    }
    __syncthreads();
    int lane = tid & 31, w = tid >> 5;
    int node = blockIdx.x*8 + w;
    if (node >= NN) return;
    int begin = d_rowptr[node], end = d_rowptr[node+1];
    float4 adv = *(const float4*)&d_adst[node*4];
    unsigned long long a01 = 0ull, a23 = 0ull;
    float dn0=0,dn1=0,dn2=0,dn3=0;
    for (int base = begin; base < end; base += 32){
        int idx = base + lane;
        int sl = 0; float4 exl = make_float4(0,0,0,0);
        if (idx < end){
            sl = d_colsrc[idx];
            float4 as = *(const float4*)&d_asrc[sl*4];
            float e0 = as.x+adv.x; e0 = e0>0.f? e0 : 0.2f*e0;
            float e1 = as.y+adv.y; e1 = e1>0.f? e1 : 0.2f*e1;
            float e2 = as.z+adv.z; e2 = e2>0.f? e2 : 0.2f*e2;
            float e3 = as.w+adv.w; e3 = e3>0.f? e3 : 0.2f*e3;
            exl = make_float4(__expf(e0),__expf(e1),__expf(e2),__expf(e3));
            dn0+=exl.x; dn1+=exl.y; dn2+=exl.z; dn3+=exl.w;
        }
        sjs[w][lane] = sl;
        *(float4*)sex[w][lane] = exl;
        __syncwarp();
        int cnt = min(32, end - base);
        int sj0 = sjs[w][0];
        ulonglong2 xv = *(const ulonglong2*)&d_xw[sj0*128 + lane*4];
        for (int j=0; j<cnt; j++){
            ulonglong2 xn = xv;
            if (j+1 < cnt){
                int sjn = sjs[w][j+1];
                xn = *(const ulonglong2*)&d_xw[sjn*128 + lane*4];
            }
            unsigned long long av = dup2(sex[w][j][lane>>3]);
            ffma2(a01, xv.x, av);
            ffma2(a23, xv.y, av);
            xv = xn;
        }
        __syncwarp();
    }
    #pragma unroll
    for (int off=16; off; off>>=1){
        dn0 += __shfl_xor_sync(FM,dn0,off); dn1 += __shfl_xor_sync(FM,dn1,off);
        dn2 += __shfl_xor_sync(FM,dn2,off); dn3 += __shfl_xor_sync(FM,dn3,off);
    }
    float2 p01 = unpack2(a01), p23 = unpack2(a23);
    float n0=p01.x, n1=p01.y, n2=p23.x, n3=p23.y;
    float4 as = *(const float4*)&d_asrc[node*4];
    float e0=as.x+adv.x; e0=e0>0.f?e0:0.2f*e0; float x0=__expf(e0);
    float e1=as.y+adv.y; e1=e1>0.f?e1:0.2f*e1; float x1=__expf(e1);
    float e2=as.z+adv.z; e2=e2>0.f?e2:0.2f*e2; float x2=__expf(e2);
    float e3=as.w+adv.w; e3=e3>0.f?e3:0.2f*e3; float x3=__expf(e3);
    dn0+=x0; dn1+=x1; dn2+=x2; dn3+=x3;
    float4 xvs = *(const float4*)&d_xw[node*128 + lane*4];
    float aself = lane<8? x0 : lane<16? x1 : lane<24? x2 : x3;
    n0 += xvs.x*aself; n1 += xvs.y*aself; n2 += xvs.z*aself; n3 += xvs.w*aself;
    float hd = lane<8? dn0 : lane<16? dn1 : lane<24? dn2 : dn3;
    float inv = 1.0f/(hd + 1e-16f);
    int col = lane*4;
    float o0 = n0*inv + gb[col];   o0 = o0>0.f? o0 : expm1f(o0); o0 = o0*sc[col]+sh[col];
    float o1 = n1*inv + gb[col+1]; o1 = o1>0.f? o1 : expm1f(o1); o1 = o1*sc[col+1]+sh[col+1];
    float o2 = n2*inv + gb[col+2]; o2 = o2>0.f? o2 : expm1f(o2); o2 = o2*sc[col+2]+sh[col+2];
    float o3 = n3*inv + gb[col+3]; o3 = o3>0.f? o3 : expm1f(o3); o3 = o3*sc[col+3]+sh[col+3];
    *(float4*)&d_h[node*128 + col] = make_float4(o0,o1,o2,o3);
}

// GCN aggregation v2: same staging/prefetch/packed-fma structure.
__global__ void k_gcn(const int* __restrict__ batch,
                      const float* __restrict__ gcnb,
                      const float* __restrict__ g2, const float* __restrict__ b2,
                      const float* __restrict__ m2, const float* __restrict__ v2,
                      const float* __restrict__ gateW, const float* __restrict__ gateb){
    __shared__ float sc[128], sh[128], gb[128], gw[128];
    __shared__ int   sjs[8][32];
    __shared__ float sds[8][32];
    int tid = threadIdx.x;
    if (tid < 128){
        float s = g2[tid]*rsqrtf(v2[tid]+1e-5f);
        sc[tid]=s; sh[tid]=b2[tid]-m2[tid]*s; gb[tid]=gcnb[tid]; gw[tid]=gateW[tid];
    }
    __syncthreads();
    int lane = tid & 31, w = tid >> 5;
    int node = blockIdx.x*8 + w;
    if (node >= NN) return;
    int begin = d_rowptr[node], end = d_rowptr[node+1];
    float did = d_dinv[node];
    unsigned long long a01 = 0ull, a23 = 0ull;
    for (int base = begin; base < end; base += 32){
        int idx = base + lane;
        int sl = 0; float dsl = 0.f;
        if (idx < end){ sl = d_colsrc[idx]; dsl = d_dinv[sl]; }
        sjs[w][lane] = sl;
        sds[w][lane] = dsl;
        __syncwarp();
        int cnt = min(32, end - base);
        int sj0 = sjs[w][0];
        ulonglong2 xv = *(const ulonglong2*)&d_hw[sj0*128 + lane*4];
        for (int j=0; j<cnt; j++){
            ulonglong2 xn = xv;
            if (j+1 < cnt){
                int sjn = sjs[w][j+1];
                xn = *(const ulonglong2*)&d_hw[sjn*128 + lane*4];
            }
            unsigned long long dv = dup2(sds[w][j]);
            ffma2(a01, xv.x, dv);
            ffma2(a23, xv.y, dv);
            xv = xn;
        }
        __syncwarp();
    }
    float2 p01 = unpack2(a01), p23 = unpack2(a23);
    int col = lane*4;
    float4 sv = *(const float4*)&d_hw[node*128 + col];
    float h0 = did*(p01.x + did*sv.x) + gb[col];
    float h1 = did*(p01.y + did*sv.y) + gb[col+1];
    float h2v = did*(p23.x + did*sv.z) + gb[col+2];
    float h3 = did*(p23.y + did*sv.w) + gb[col+3];
    h0 = h0>0.f? h0 : expm1f(h0); h0 = h0*sc[col]+sh[col];
    h1 = h1>0.f? h1 : expm1f(h1); h1 = h1*sc[col+1]+sh[col+1];
    h2v = h2v>0.f? h2v : expm1f(h2v); h2v = h2v*sc[col+2]+sh[col+2];
    h3 = h3>0.f? h3 : expm1f(h3); h3 = h3*sc[col+3]+sh[col+3];
    float g = h0*gw[col] + h1*gw[col+1] + h2v*gw[col+2] + h3*gw[col+3];
    #pragma unroll
    for (int off=16; off; off>>=1) g += __shfl_xor_sync(FM, g, off);
    g += gateb[0];
    float p = __expf(g);
    int b = batch[node];
    if (lane == 0) atomicAdd(&d_gden[b], p);
    atomicAdd(&d_gnum[b*128+col],   p*h0);
    atomicAdd(&d_gnum[b*128+col+1], p*h1);
    atomicAdd(&d_gnum[b*128+col+2], p*h2v);
    atomicAdd(&d_gnum[b*128+col+3], p*h3);
}

__global__ void k_xp(const float* __restrict__ quant, const float* __restrict__ Wih,
                     const float* __restrict__ bih, const float* __restrict__ bhh){
    __shared__ float qS[TSTEPS*32];
    int b = blockIdx.x, g = threadIdx.x;
    for (int i = g; i < TSTEPS*32; i += 512) qS[i] = quant[b*TSTEPS*32 + i];
    float4 wr[8];
    #pragma unroll
    for (int q=0;q<8;q++) wr[q] = *(const float4*)&Wih[g*32 + q*4];
    float bias = bih[g] + bhh[g];
    __syncthreads();
    const float4* qS4 = (const float4*)qS;
    for (int t=0; t<TSTEPS; t++){
        float acc = bias;
        #pragma unroll
        for (int q=0;q<8;q++){
            float4 xv = qS4[t*8+q];
            acc += wr[q].x*xv.x + wr[q].y*xv.y + wr[q].z*xv.z + wr[q].w*xv.w;
        }
        d_xp[(b*TSTEPS + t)*512 + g] = acc;
    }
}

// LSTM v3 (unchanged from R12)
__global__ void __cluster_dims__(2,1,1) __launch_bounds__(256,1)
k_lstmp(const float* __restrict__ Whh){
    __shared__ __align__(16) float hps[512];
    __shared__ float gbuf[1024];
    int tid = threadIdx.x;
    unsigned int rank;
    asm("mov.u32 %0, %%cluster_ctarank;" : "=r"(rank));
    int U0 = (int)rank * 64;
    int b0 = (blockIdx.x >> 1) * 4;
    int g = tid >> 6, ju = tid & 63;
    int row = g*128 + U0 + ju;

    union { unsigned long long u[64]; float4 v[32]; } W;
    {
        const float4* row4 = (const float4*)&Whh[row*128];
        #pragma unroll
        for (int j=0;j<32;j++) W.v[j] = row4[j];
    }
    for (int i = tid; i < 512; i += 256) hps[i] = 0.f;
    float creg = 0.f;
    __syncthreads();
    asm volatile("barrier.cluster.arrive.aligned;" ::: "memory");
    asm volatile("barrier.cluster.wait.aligned;" ::: "memory");

    unsigned int hps_addr;
    asm("{ .reg .u64 t; cvta.to.shared.u64 t, %1; cvt.u32.u64 %0, t; }" : "=r"(hps_addr) : "l"(hps));
    unsigned int peer = rank ^ 1u;
    unsigned int hps_peer;
    asm("mapa.shared::cluster.u32 %0, %1, %2;" : "=r"(hps_peer) : "r"(hps_addr), "r"(peer));

    const ulonglong2* hp4 = (const ulonglong2*)hps;
    int ub = tid >> 6, uju = tid & 63;
    int hk = U0 + uju;
    int woff = (hk>>1)*8 + (ub>>1)*4 + (ub&1)*2 + (hk&1);

    for (int t=0; t<TSTEPS; t++){
        float x0 = d_xp[((b0+0)*TSTEPS + t)*512 + row];
        float x1 = d_xp[((b0+1)*TSTEPS + t)*512 + row];
        float x2 = d_xp[((b0+2)*TSTEPS + t)*512 + row];
        float x3 = d_xp[((b0+3)*TSTEPS + t)*512 + row];
        unsigned long long a0=0,a1=0,a2=0,a3=0;
        #pragma unroll
        for (int k2=0;k2<64;k2++){
            ulonglong2 hA = hp4[2*k2];
            ulonglong2 hB = hp4[2*k2+1];
            ffma2(a0, W.u[k2], hA.x);
            ffma2(a1, W.u[k2], hA.y);
            ffma2(a2, W.u[k2], hB.x);
            ffma2(a3, W.u[k2], hB.y);
        }
        ((float4*)gbuf)[tid] = make_float4(pairsum(a0)+x0, pairsum(a1)+x1,
                                           pairsum(a2)+x2, pairsum(a3)+x3);
        __syncthreads();
        float gi = gbuf[(0*64+uju)*4 + ub];
        float gf = gbuf[(1*64+uju)*4 + ub];
        float gg = gbuf[(2*64+uju)*4 + ub];
        float go = gbuf[(3*64+uju)*4 + ub];
        float cn = sigf(gf)*creg + sigf(gi)*tanhfa(gg);
        creg = cn;
        float hn = sigf(go)*tanhfa(cn);
        hps[woff] = hn;
        asm volatile("st.shared::cluster.f32 [%0], %1;" :: "r"(hps_peer + woff*4), "f"(hn) : "memory");
        if (t == TSTEPS-1) d_hT[(b0+ub)*128 + hk] = hn;
        asm volatile("barrier.cluster.arrive.aligned;" ::: "memory");
        asm volatile("barrier.cluster.wait.aligned;" ::: "memory");
    }
}

__global__ void k_fin(const float* __restrict__ fcW, const float* __restrict__ fcb,
                      float* __restrict__ out){
    __shared__ float r[128];
    int b = blockIdx.x, tid = threadIdx.x;
    float rep = d_gnum[b*128+tid] / (d_gden[b] + 1e-16f);
    float v = fcW[tid]*rep + fcW[128+tid]*d_hT[b*128+tid];
    r[tid] = v; __syncthreads();
    for (int off=64; off; off>>=1){
        if (tid < off) r[tid] += r[tid+off];
        __syncthreads();
    }
    if (tid == 0) out[b] = r[0] + fcb[0];
}

extern "C" void kernel_launch(void* const* d_in, const int* in_sizes, int n_in,
                              void* d_out, int out_size){
    const float* x      = (const float*)d_in[0];
    const int*   ei     = (const int*)  d_in[1];
    const int*   batch  = (const int*)  d_in[2];
    const float* quant  = (const float*)d_in[3];
    const float* gatW   = (const float*)d_in[4];
    const float* attS   = (const float*)d_in[5];
    const float* attD   = (const float*)d_in[6];
    const float* gatb   = (const float*)d_in[7];
    const float* g1     = (const float*)d_in[8];
    const float* b1     = (const float*)d_in[9];
    const float* m1     = (const float*)d_in[10];
    const float* v1     = (const float*)d_in[11];
    const float* gcnW   = (const float*)d_in[12];
    const float* gcnb   = (const float*)d_in[13];
    const float* g2     = (const float*)d_in[14];
    const float* b2     = (const float*)d_in[15];
    const float* m2     = (const float*)d_in[16];
    const float* v2     = (const float*)d_in[17];
    const float* gateW  = (const float*)d_in[18];
    const float* gateb  = (const float*)d_in[19];
    const float* Wih    = (const float*)d_in[20];
    const float* Whh    = (const float*)d_in[21];
    const float* bih    = (const float*)d_in[22];
    const float* bhh    = (const float*)d_in[23];
    const float* fcW    = (const float*)d_in[24];
    const float* fcb    = (const float*)d_in[25];
    float* out = (float*)d_out;

    cudaFuncSetAttribute(k_gemm, cudaFuncAttributeMaxDynamicSharedMemorySize, 98304);

    cudaStream_t sA, sB;
    cudaStreamCreateWithFlags(&sA, cudaStreamNonBlocking);
    cudaStreamCreateWithFlags(&sB, cudaStreamNonBlocking);
    cudaEvent_t eFork, eCsr, eLstm;
    cudaEventCreateWithFlags(&eFork, cudaEventDisableTiming);
    cudaEventCreateWithFlags(&eCsr,  cudaEventDisableTiming);
    cudaEventCreateWithFlags(&eLstm, cudaEventDisableTiming);

    cudaEventRecord(eFork, 0);
    cudaStreamWaitEvent(sA, eFork, 0);
    cudaStreamWaitEvent(sB, eFork, 0);

    // enqueue order: slot 4 (ncu capture) = k_lstmp this round
    k_xp<<<256,512,0,sB>>>(quant, Wih, bih, bhh);          // 1
    k_init<<<196,256,0,sA>>>();                            // 2
    k_count<<<3125,256,0,sA>>>(ei);                        // 3
    k_lstmp<<<128,256,0,sB>>>(Whh);                        // 4  <-- profiled
    cudaEventRecord(eLstm, sB);
    k_scan1<<<196,256,0,sA>>>();                           // 5
    k_scan2<<<1,256,0,sA>>>();                             // 6
    k_scan3<<<196,256,0,sA>>>();                           // 7
    k_prep<<<196,256,0,sA>>>();                            // 8
    k_scatter<<<3125,256,0,sA>>>(ei);                      // 9
    cudaEventRecord(eCsr, sA);
    k_gemm<<<296,256,98304>>>(x, gatW, attS, attD, 0);     // 10 (starts at t=0 on s0)

    cudaStreamWaitEvent(0, eCsr, 0);
    k_gat<<<6250,256>>>(gatb, g1, b1, m1, v1);             // 11
    k_gemm<<<296,256,98304>>>(nullptr, gcnW, nullptr, nullptr, 1);  // 12
    k_gcn<<<6250,256>>>(batch, gcnb, g2, b2, m2, v2, gateW, gateb); // 13

    cudaStreamWaitEvent(0, eLstm, 0);
    k_fin<<<256,128>>>(fcW, fcb, out);                     // 14

    cudaStreamDestroy(sA);
    cudaStreamDestroy(sB);
    cudaEventDestroy(eFork);
    cudaEventDestroy(eCsr);
    cudaEventDestroy(eLstm);
    (void)in_sizes; (void)n_in; (void)out_size;
}